// round 5
// baseline (speedup 1.0000x reference)
#include <cuda_runtime.h>
#include <cuda_bf16.h>
#include <math.h>

// ---------------- problem constants ----------------
#define NB 2
#define NV 3
#define NC 32
#define ND 48
#define NH 128
#define NW 160
#define NHW (NH*NW)          // 20480

// ---------------- fused kernel tiling ----------------
#define TH 8
#define TW 32
#define HHs (TH+2)           // 10
#define HWs (TW+2)           // 34
#define PLANE (HHs*HWs)      // 340
#define CH 12                // depth outputs per block
#define NCH (ND/CH)          // 4

// smem layout (bytes)
#define OFF_VAR   0                       // float4 sVar[8][PLANE]      43520
#define OFF_OFF   43520                   // int4   sOff[2][PLANE]      10880
#define OFF_WGT   54400                   // u64    sWgt[2][PLANE][4]   21760
#define OFF_RIX   76160                   // int    sRefIdx[PLANE]       1360
#define OFF_WC    77520                   // u64    sWc[432]             3456
#define SMEM_BYTES 80976                  // -> 2 blocks/SM

typedef unsigned long long ull;

// ---------------- device scratch ----------------
// Feature layout: (V, B, CG=8, H, W, 4ch) fp32, pixel stride 16B
__device__ __align__(128) float g_featT[(size_t)NV*NB*NHW*NC];
__device__ float g_cost[(size_t)NB*ND*NHW];
__device__ float g_rot[NB][2][9];
__device__ float g_trans[NB][2][3];
__device__ __align__(16) float g_wcf[864];   // packed conv weights, see prep
__device__ float g_bias;

#define CG_PLANE ((size_t)NHW)
#define VB_STRIDE ((size_t)8*NHW)

// ---------------- packed f32x2 helpers ----------------
__device__ __forceinline__ ull fma2(ull a, ull b, ull c) {
    ull d; asm("fma.rn.f32x2 %0, %1, %2, %3;" : "=l"(d) : "l"(a), "l"(b), "l"(c)); return d;
}
__device__ __forceinline__ ull mul2(ull a, ull b) {
    ull d; asm("mul.rn.f32x2 %0, %1, %2;" : "=l"(d) : "l"(a), "l"(b)); return d;
}
__device__ __forceinline__ ull add2(ull a, ull b) {
    ull d; asm("add.rn.f32x2 %0, %1, %2;" : "=l"(d) : "l"(a), "l"(b)); return d;
}
__device__ __forceinline__ ull dup2(float f) {
    ull d; int r = __float_as_int(f);
    asm("mov.b64 %0, {%1, %1};" : "=l"(d) : "r"(r)); return d;
}
__device__ __forceinline__ float sum2(ull v) {
    int lo, hi; asm("mov.b64 {%0, %1}, %2;" : "=r"(lo), "=r"(hi) : "l"(v));
    return __int_as_float(lo) + __int_as_float(hi);
}
#define NEGMASK 0x8000000080000000ULL
#define INV3P   0x3eaaaaab3eaaaaabULL   // (1/3, 1/3)

// ---------------- prep: proj @ inv(ref_proj), weight relayout ----------------
__global__ void prep_kernel(const float* __restrict__ proj,
                            const float* __restrict__ rw,
                            const float* __restrict__ rb) {
    int tid = threadIdx.x;
    // rw layout (1,C,3,3,3): rw[c*27 + kd*9 + kh*3 + kw]
    // g_wcf float idx = (cg*9 + kh*3 + kw)*12 + kd*4 + pr*2 + lane
    for (int i = tid; i < 27*NC; i += blockDim.x) {
        int c = i / 27, k = i - c*27;
        int kd = k / 9, kh = (k - kd*9) / 3, kw = k % 3;
        int cg = c >> 2, c4 = c & 3, pr = c4 >> 1, lane = c4 & 1;
        g_wcf[(cg*9 + kh*3 + kw)*12 + kd*4 + pr*2 + lane] = rw[i];
    }
    if (tid == 0) g_bias = rb[0];
    if (tid < NB) {
        int b = tid;
        const float* refp = proj + ((size_t)b*NV + 0)*16;
        double a[4][8];
        for (int r = 0; r < 4; r++)
            for (int c2 = 0; c2 < 4; c2++) {
                a[r][c2] = (double)refp[r*4+c2];
                a[r][4+c2] = (r == c2) ? 1.0 : 0.0;
            }
        for (int col = 0; col < 4; col++) {
            int p = col; double best = fabs(a[col][col]);
            for (int r = col+1; r < 4; r++) {
                double v = fabs(a[r][col]);
                if (v > best) { best = v; p = r; }
            }
            if (p != col)
                for (int c2 = 0; c2 < 8; c2++) {
                    double t = a[col][c2]; a[col][c2] = a[p][c2]; a[p][c2] = t;
                }
            double pi = 1.0 / a[col][col];
            for (int c2 = 0; c2 < 8; c2++) a[col][c2] *= pi;
            for (int r = 0; r < 4; r++) if (r != col) {
                double f = a[r][col];
                for (int c2 = 0; c2 < 8; c2++) a[r][c2] -= f*a[col][c2];
            }
        }
        for (int v = 1; v < NV; v++) {
            const float* S = proj + ((size_t)b*NV + v)*16;
            for (int r = 0; r < 3; r++) {
                double pr[4];
                for (int c2 = 0; c2 < 4; c2++) {
                    double s = 0.0;
                    for (int k = 0; k < 4; k++) s += (double)S[r*4+k]*a[k][4+c2];
                    pr[c2] = s;
                }
                g_rot[b][v-1][r*3+0] = (float)pr[0];
                g_rot[b][v-1][r*3+1] = (float)pr[1];
                g_rot[b][v-1][r*3+2] = (float)pr[2];
                g_trans[b][v-1][r]   = (float)pr[3];
            }
        }
    }
}

// ---------------- transpose (V,B,C,H,W) -> (V,B,cg,H,W,4) ----------------
__global__ void transpose_kernel(const float* __restrict__ feat) {
    __shared__ float t[32][33];
    int vb = blockIdx.y;
    int hw0 = blockIdx.x * 32;
    const float* src = feat + (size_t)vb*NC*NHW;
    #pragma unroll
    for (int cc = threadIdx.y; cc < 32; cc += 8)
        t[cc][threadIdx.x] = src[(size_t)cc*NHW + hw0 + threadIdx.x];
    __syncthreads();
    float* dst = g_featT + (size_t)vb*VB_STRIDE*4;
    int c = threadIdx.x;
    int cg = c >> 2, c4 = c & 3;
    #pragma unroll
    for (int r = threadIdx.y; r < 32; r += 8)
        dst[((size_t)cg*CG_PLANE + hw0 + r)*4 + c4] = t[c][r];
}

// ---------------- fused warp + variance + conv3d (depth ring) ----------------
__global__ __launch_bounds__(256, 2)
void fused_cost_kernel(const float* __restrict__ dvals) {
    extern __shared__ unsigned char smem_raw[];
    ulonglong2* sVar = (ulonglong2*)(smem_raw + OFF_VAR);     // [cg][p] (2x ch-pair)
    int4*       sOff = (int4*)(smem_raw + OFF_OFF);           // [view][p]
    ull*        sWgt = (ull*)(smem_raw + OFF_WGT);            // [view][p][4] dup-packed
    int*        sRix = (int*)(smem_raw + OFF_RIX);            // [p] ref pixel idx / -1
    ull*        sWc  = (ull*)(smem_raw + OFF_WC);             // 432 u64 conv weights

    const int tid = threadIdx.x;
    const int b  = blockIdx.z / NCH;
    const int d0 = (blockIdx.z - b*NCH) * CH;
    const int h0 = blockIdx.y * TH;
    const int w0 = blockIdx.x * TW;

    for (int i = tid; i < 864; i += 256) ((float*)sWc)[i] = g_wcf[i];

    float R[2][9], T[2][3];
    #pragma unroll
    for (int v = 0; v < 2; v++) {
        #pragma unroll
        for (int k = 0; k < 9; k++) R[v][k] = g_rot[b][v][k];
        #pragma unroll
        for (int k = 0; k < 3; k++) T[v][k] = g_trans[b][v][k];
    }

    const ulonglong2* refBase = (const ulonglong2*)g_featT + (size_t)(0*NB + b)*VB_STRIDE;
    const ulonglong2* v1Base  = (const ulonglong2*)g_featT + (size_t)(1*NB + b)*VB_STRIDE;
    const ulonglong2* v2Base  = (const ulonglong2*)g_featT + (size_t)(2*NB + b)*VB_STRIDE;

    const int lh = tid >> 5;       // 0..7
    const int lw = tid & 31;       // 0..31
    const float bias = g_bias;

    ull aN = 0, aC = 0, aP = 0;    // ring accumulators (packed pairs)

    for (int s = d0 - 1; s <= d0 + CH; s++) {
        const bool active = (s >= 0 && s < ND);
        if (active) {
            const float dep = __ldg(&dvals[b*ND + s]);
            // ---- descriptors: once per (p, slice), shared by 8 cg ----
            for (int p = tid; p < PLANE; p += 256) {
                int hh = p / HWs, ww = p - hh*HWs;
                int h = h0 + hh - 1, w = w0 + ww - 1;
                bool valid = ((unsigned)h < (unsigned)NH && (unsigned)w < (unsigned)NW);
                sRix[p] = valid ? (h*NW + w) : -1;
                if (!valid) continue;
                float fx = (float)w, fy = (float)h;
                #pragma unroll
                for (int v = 0; v < 2; v++) {
                    float rx = R[v][0]*fx + R[v][1]*fy + R[v][2];
                    float ry = R[v][3]*fx + R[v][4]*fy + R[v][5];
                    float rz = R[v][6]*fx + R[v][7]*fy + R[v][8];
                    float px = rx*dep + T[v][0];
                    float py = ry*dep + T[v][1];
                    float pz = rz*dep + T[v][2];
                    if (fabsf(pz) < 1e-6f) pz = 1e-6f;
                    px = px / pz;
                    py = py / pz;
                    float x0f = floorf(px), y0f = floorf(py);
                    float wx1 = px - x0f, wy1 = py - y0f;
                    float wx0 = 1.f - wx1, wy0 = 1.f - wy1;
                    float x1f = x0f + 1.f, y1f = y0f + 1.f;
                    float vx0 = (x0f >= 0.f && x0f <= (float)(NW-1)) ? 1.f : 0.f;
                    float vx1 = (x1f >= 0.f && x1f <= (float)(NW-1)) ? 1.f : 0.f;
                    float vy0 = (y0f >= 0.f && y0f <= (float)(NH-1)) ? 1.f : 0.f;
                    float vy1 = (y1f >= 0.f && y1f <= (float)(NH-1)) ? 1.f : 0.f;
                    int ix0 = (int)fminf(fmaxf(x0f, 0.f), (float)(NW-1));
                    int ix1 = (int)fminf(fmaxf(x1f, 0.f), (float)(NW-1));
                    int iy0 = (int)fminf(fmaxf(y0f, 0.f), (float)(NH-1));
                    int iy1 = (int)fminf(fmaxf(y1f, 0.f), (float)(NH-1));
                    sOff[v*PLANE + p] = make_int4(iy0*NW+ix0, iy0*NW+ix1, iy1*NW+ix0, iy1*NW+ix1);
                    ull* wp = sWgt + (size_t)(v*PLANE + p)*4;
                    wp[0] = dup2(wx0*wy0*vx0*vy0);
                    wp[1] = dup2(wx1*wy0*vx1*vy0);
                    wp[2] = dup2(wx0*wy1*vx0*vy1);
                    wp[3] = dup2(wx1*wy1*vx1*vy1);
                }
            }
            __syncthreads();
            // ---- variance slice, all 8 cg (packed pairs) ----
            for (int i = tid; i < 8*PLANE; i += 256) {
                int cg = i / PLANE, p = i - cg*PLANE;
                int ro = sRix[p];
                ulonglong2 outv;
                if (ro < 0) { outv.x = 0; outv.y = 0; }
                else {
                    ulonglong2 r = refBase[(size_t)cg*CG_PLANE + ro];
                    ull s01 = r.x, s23 = r.y;
                    ull q01 = mul2(r.x, r.x), q23 = mul2(r.y, r.y);
                    {
                        int4 o = sOff[p];
                        const ull* wp = sWgt + (size_t)p*4;
                        ull w00 = wp[0], w01 = wp[1], w10 = wp[2], w11 = wp[3];
                        const ulonglong2* bp = v1Base + (size_t)cg*CG_PLANE;
                        ulonglong2 f00 = bp[o.x], f01 = bp[o.y], f10 = bp[o.z], f11 = bp[o.w];
                        ull a01 = mul2(f00.x, w00); a01 = fma2(f01.x, w01, a01);
                        a01 = fma2(f10.x, w10, a01); a01 = fma2(f11.x, w11, a01);
                        ull a23 = mul2(f00.y, w00); a23 = fma2(f01.y, w01, a23);
                        a23 = fma2(f10.y, w10, a23); a23 = fma2(f11.y, w11, a23);
                        s01 = add2(s01, a01); q01 = fma2(a01, a01, q01);
                        s23 = add2(s23, a23); q23 = fma2(a23, a23, q23);
                    }
                    {
                        int4 o = sOff[PLANE + p];
                        const ull* wp = sWgt + (size_t)(PLANE + p)*4;
                        ull w00 = wp[0], w01 = wp[1], w10 = wp[2], w11 = wp[3];
                        const ulonglong2* bp = v2Base + (size_t)cg*CG_PLANE;
                        ulonglong2 f00 = bp[o.x], f01 = bp[o.y], f10 = bp[o.z], f11 = bp[o.w];
                        ull a01 = mul2(f00.x, w00); a01 = fma2(f01.x, w01, a01);
                        a01 = fma2(f10.x, w10, a01); a01 = fma2(f11.x, w11, a01);
                        ull a23 = mul2(f00.y, w00); a23 = fma2(f01.y, w01, a23);
                        a23 = fma2(f10.y, w10, a23); a23 = fma2(f11.y, w11, a23);
                        s01 = add2(s01, a01); q01 = fma2(a01, a01, q01);
                        s23 = add2(s23, a23); q23 = fma2(a23, a23, q23);
                    }
                    ull m01 = mul2(s01, INV3P), m23 = mul2(s23, INV3P);
                    ull nm01 = m01 ^ NEGMASK,  nm23 = m23 ^ NEGMASK;
                    outv.x = fma2(nm01, m01, mul2(q01, INV3P));
                    outv.y = fma2(nm23, m23, mul2(q23, INV3P));
                }
                sVar[i] = outv;
            }
            __syncthreads();
            // ---- conv contributions of this slice (packed) ----
            #pragma unroll 1
            for (int cg = 0; cg < 8; cg++) {
                const ulonglong2* vb = sVar + cg*PLANE + lh*HWs + lw;
                const ulonglong2* wb = (const ulonglong2*)sWc + cg*27;
                #pragma unroll
                for (int kh = 0; kh < 3; kh++) {
                    #pragma unroll
                    for (int kw = 0; kw < 3; kw++) {
                        ulonglong2 v = vb[kh*HWs + kw];
                        const ulonglong2* wp = wb + (kh*3 + kw)*3;
                        ulonglong2 w0 = wp[0], w1 = wp[1], w2 = wp[2];
                        aN = fma2(v.x, w0.x, aN); aN = fma2(v.y, w0.y, aN);  // kd=0 -> out s+1
                        aC = fma2(v.x, w1.x, aC); aC = fma2(v.y, w1.y, aC);  // kd=1 -> out s
                        aP = fma2(v.x, w2.x, aP); aP = fma2(v.y, w2.y, aP);  // kd=2 -> out s-1
                    }
                }
            }
        }
        // emit completed output o = s-1
        int o = s - 1;
        if (o >= d0 && o < d0 + CH) {
            g_cost[(((size_t)b*ND + o)*NH + (h0 + lh))*NW + w0 + lw] = sum2(aP) + bias;
        }
        aP = aC; aC = aN; aN = 0;
    }
}

// ---------------- softmax over depth + expected depth + confidence ----------------
__global__ __launch_bounds__(256)
void softmax_kernel(const float* __restrict__ dvals, float* __restrict__ out) {
    int gid = blockIdx.x*blockDim.x + threadIdx.x;
    if (gid >= NB*NHW) return;
    int b = gid / NHW;
    int hw = gid - b*NHW;
    const float* cp = g_cost + (size_t)b*ND*NHW + hw;
    float c[ND];
    float mx = -3.4e38f;
    #pragma unroll
    for (int d = 0; d < ND; d++) {
        c[d] = cp[(size_t)d*NHW];
        mx = fmaxf(mx, c[d]);
    }
    float sum = 0.f;
    #pragma unroll
    for (int d = 0; d < ND; d++) {
        c[d] = __expf(c[d] - mx);
        sum += c[d];
    }
    float inv = 1.f/sum;
    float depth = 0.f, fidx = 0.f;
    #pragma unroll
    for (int d = 0; d < ND; d++) {
        depth += c[d]*__ldg(&dvals[b*ND + d]);
        fidx  += c[d]*(float)d;
    }
    depth *= inv;
    fidx  *= inv;
    int di = (int)fidx;
    di = min(max(di, 0), ND-1);
    float conf = 0.f;
    #pragma unroll
    for (int d = 0; d < ND; d++) {
        if (d >= di-1 && d <= di+2) conf += c[d];
    }
    conf *= inv;
    out[gid] = depth;
    out[NB*NHW + gid] = conf;
}

// ---------------- launch ----------------
extern "C" void kernel_launch(void* const* d_in, const int* in_sizes, int n_in,
                              void* d_out, int out_size) {
    const float* features = (const float*)d_in[0];   // (V,B,C,H,W)
    const float* proj     = (const float*)d_in[1];   // (B,V,4,4)
    const float* dvals    = (const float*)d_in[2];   // (B,D)
    int iw = 3;
    while (iw < n_in && in_sizes[iw] != 27*NC) iw++;
    const float* rw = (const float*)d_in[iw];
    const float* rb = (const float*)d_in[iw+1];

    cudaFuncSetAttribute(fused_cost_kernel,
                         cudaFuncAttributeMaxDynamicSharedMemorySize, SMEM_BYTES);

    prep_kernel<<<1, 256>>>(proj, rw, rb);
    transpose_kernel<<<dim3(NHW/32, NV*NB), dim3(32, 8)>>>(features);
    fused_cost_kernel<<<dim3(NW/TW, NH/TH, NB*NCH), 256, SMEM_BYTES>>>(dvals);
    softmax_kernel<<<(NB*NHW + 255)/256, 256>>>(dvals, (float*)d_out);
}

// round 7
// speedup vs baseline: 1.5645x; 1.5645x over previous
#include <cuda_runtime.h>
#include <cuda_bf16.h>
#include <math.h>

// ---------------- problem constants ----------------
#define NB 2
#define NV 3
#define NC 32
#define ND 48
#define NH 128
#define NW 160
#define NHW (NH*NW)          // 20480

// ---------------- fused kernel tiling ----------------
#define TD 6
#define TH 8
#define TW 32
#define HD (TD+2)            // 8
#define HHs (TH+2)           // 10
#define HWs (TW+2)           // 34
#define PLANE (HHs*HWs)      // 340
#define NHALO (HD*PLANE)     // 2720
#define NCHUNK (ND/TD)       // 8

// smem layout (bytes): sVar[2][NHALO] ulonglong2 + sPos[NHALO] float4 + sWc
#define OFF_POS  (2*NHALO*16)            // 87040
#define OFF_WC   (OFF_POS + NHALO*16)    // 130560
#define SMEM_BYTES (OFF_WC + 432*8)      // 134016 -> 1 block of 512/SM

typedef unsigned long long ull;

// ---------------- device scratch ----------------
// Feature layout: (V, B, CG=8, H, W, 4ch) fp32, pixel stride 16B
__device__ __align__(128) float g_featT[(size_t)NV*NB*NHW*NC];
__device__ float g_cost[(size_t)NB*ND*NHW];
__device__ float g_rot[NB][2][9];
__device__ float g_trans[NB][2][3];
__device__ __align__(16) float g_wcf[864];   // packed conv weights
__device__ float g_bias;

#define CG_PLANE ((size_t)NHW)
#define VB_STRIDE ((size_t)8*NHW)

// ---------------- packed f32x2 helpers ----------------
__device__ __forceinline__ ull fma2(ull a, ull b, ull c) {
    ull d; asm("fma.rn.f32x2 %0, %1, %2, %3;" : "=l"(d) : "l"(a), "l"(b), "l"(c)); return d;
}
__device__ __forceinline__ ull mul2(ull a, ull b) {
    ull d; asm("mul.rn.f32x2 %0, %1, %2;" : "=l"(d) : "l"(a), "l"(b)); return d;
}
__device__ __forceinline__ ull add2(ull a, ull b) {
    ull d; asm("add.rn.f32x2 %0, %1, %2;" : "=l"(d) : "l"(a), "l"(b)); return d;
}
__device__ __forceinline__ ull dup2(float f) {
    ull d; int r = __float_as_int(f);
    asm("mov.b64 %0, {%1, %1};" : "=l"(d) : "r"(r)); return d;
}
__device__ __forceinline__ float sum2(ull v) {
    int lo, hi; asm("mov.b64 {%0, %1}, %2;" : "=r"(lo), "=r"(hi) : "l"(v));
    return __int_as_float(lo) + __int_as_float(hi);
}
#define NEGMASK 0x8000000080000000ULL
#define INV3P   0x3eaaaaab3eaaaaabULL   // (1/3, 1/3)

// ---------------- prep ----------------
__global__ void prep_kernel(const float* __restrict__ proj,
                            const float* __restrict__ rw,
                            const float* __restrict__ rb) {
    int tid = threadIdx.x;
    // rw layout (1,C,3,3,3): rw[c*27 + kd*9 + kh*3 + kw]
    // g_wcf float idx = (cg*9 + kh*3 + kw)*12 + kd*4 + pr*2 + lane
    for (int i = tid; i < 27*NC; i += blockDim.x) {
        int c = i / 27, k = i - c*27;
        int kd = k / 9, kh = (k - kd*9) / 3, kw = k % 3;
        int cg = c >> 2, c4 = c & 3, pr = c4 >> 1, lane = c4 & 1;
        g_wcf[(cg*9 + kh*3 + kw)*12 + kd*4 + pr*2 + lane] = rw[i];
    }
    if (tid == 0) g_bias = rb[0];
    if (tid < NB) {
        int b = tid;
        const float* refp = proj + ((size_t)b*NV + 0)*16;
        double a[4][8];
        for (int r = 0; r < 4; r++)
            for (int c2 = 0; c2 < 4; c2++) {
                a[r][c2] = (double)refp[r*4+c2];
                a[r][4+c2] = (r == c2) ? 1.0 : 0.0;
            }
        for (int col = 0; col < 4; col++) {
            int p = col; double best = fabs(a[col][col]);
            for (int r = col+1; r < 4; r++) {
                double v = fabs(a[r][col]);
                if (v > best) { best = v; p = r; }
            }
            if (p != col)
                for (int c2 = 0; c2 < 8; c2++) {
                    double t = a[col][c2]; a[col][c2] = a[p][c2]; a[p][c2] = t;
                }
            double pi = 1.0 / a[col][col];
            for (int c2 = 0; c2 < 8; c2++) a[col][c2] *= pi;
            for (int r = 0; r < 4; r++) if (r != col) {
                double f = a[r][col];
                for (int c2 = 0; c2 < 8; c2++) a[r][c2] -= f*a[col][c2];
            }
        }
        for (int v = 1; v < NV; v++) {
            const float* S = proj + ((size_t)b*NV + v)*16;
            for (int r = 0; r < 3; r++) {
                double pr[4];
                for (int c2 = 0; c2 < 4; c2++) {
                    double s = 0.0;
                    for (int k = 0; k < 4; k++) s += (double)S[r*4+k]*a[k][4+c2];
                    pr[c2] = s;
                }
                g_rot[b][v-1][r*3+0] = (float)pr[0];
                g_rot[b][v-1][r*3+1] = (float)pr[1];
                g_rot[b][v-1][r*3+2] = (float)pr[2];
                g_trans[b][v-1][r]   = (float)pr[3];
            }
        }
    }
}

// ---------------- transpose (V,B,C,H,W) -> (V,B,cg,H,W,4) ----------------
__global__ void transpose_kernel(const float* __restrict__ feat) {
    __shared__ float t[32][33];
    int vb = blockIdx.y;
    int hw0 = blockIdx.x * 32;
    const float* src = feat + (size_t)vb*NC*NHW;
    #pragma unroll
    for (int cc = threadIdx.y; cc < 32; cc += 8)
        t[cc][threadIdx.x] = src[(size_t)cc*NHW + hw0 + threadIdx.x];
    __syncthreads();
    float* dst = g_featT + (size_t)vb*VB_STRIDE*4;
    int c = threadIdx.x;
    int cg = c >> 2, c4 = c & 3;
    #pragma unroll
    for (int r = threadIdx.y; r < 32; r += 8)
        dst[((size_t)cg*CG_PLANE + hw0 + r)*4 + c4] = t[c][r];
}

// ---------------- bilinear interp of a cg-pair (8 channels, one view) ----------------
__device__ __forceinline__ void interp_pair(
    const ulonglong2* __restrict__ bpA, const ulonglong2* __restrict__ bpB,
    float px, float py,
    ull& sA01, ull& sA23, ull& qA01, ull& qA23,
    ull& sB01, ull& sB23, ull& qB01, ull& qB23)
{
    float x0f = floorf(px), y0f = floorf(py);
    float wx1 = px - x0f, wy1 = py - y0f;
    float wx0 = 1.f - wx1, wy0 = 1.f - wy1;
    float x1f = x0f + 1.f, y1f = y0f + 1.f;
    float vx0 = (x0f >= 0.f && x0f <= (float)(NW-1)) ? 1.f : 0.f;
    float vx1 = (x1f >= 0.f && x1f <= (float)(NW-1)) ? 1.f : 0.f;
    float vy0 = (y0f >= 0.f && y0f <= (float)(NH-1)) ? 1.f : 0.f;
    float vy1 = (y1f >= 0.f && y1f <= (float)(NH-1)) ? 1.f : 0.f;
    int ix0 = (int)fminf(fmaxf(x0f, 0.f), (float)(NW-1));
    int ix1 = (int)fminf(fmaxf(x1f, 0.f), (float)(NW-1));
    int iy0 = (int)fminf(fmaxf(y0f, 0.f), (float)(NH-1));
    int iy1 = (int)fminf(fmaxf(y1f, 0.f), (float)(NH-1));
    ull W00 = dup2(wx0*wy0*vx0*vy0);
    ull W01 = dup2(wx1*wy0*vx1*vy0);
    ull W10 = dup2(wx0*wy1*vx0*vy1);
    ull W11 = dup2(wx1*wy1*vx1*vy1);
    int o00 = iy0*NW + ix0, o01 = iy0*NW + ix1;
    int o10 = iy1*NW + ix0, o11 = iy1*NW + ix1;
    {
        ulonglong2 f00 = __ldg(bpA + o00), f01 = __ldg(bpA + o01);
        ulonglong2 f10 = __ldg(bpA + o10), f11 = __ldg(bpA + o11);
        ull a01 = mul2(f00.x, W00); a01 = fma2(f01.x, W01, a01);
        a01 = fma2(f10.x, W10, a01); a01 = fma2(f11.x, W11, a01);
        ull a23 = mul2(f00.y, W00); a23 = fma2(f01.y, W01, a23);
        a23 = fma2(f10.y, W10, a23); a23 = fma2(f11.y, W11, a23);
        sA01 = add2(sA01, a01); qA01 = fma2(a01, a01, qA01);
        sA23 = add2(sA23, a23); qA23 = fma2(a23, a23, qA23);
    }
    {
        ulonglong2 f00 = __ldg(bpB + o00), f01 = __ldg(bpB + o01);
        ulonglong2 f10 = __ldg(bpB + o10), f11 = __ldg(bpB + o11);
        ull a01 = mul2(f00.x, W00); a01 = fma2(f01.x, W01, a01);
        a01 = fma2(f10.x, W10, a01); a01 = fma2(f11.x, W11, a01);
        ull a23 = mul2(f00.y, W00); a23 = fma2(f01.y, W01, a23);
        a23 = fma2(f10.y, W10, a23); a23 = fma2(f11.y, W11, a23);
        sB01 = add2(sB01, a01); qB01 = fma2(a01, a01, qB01);
        sB23 = add2(sB23, a23); qB23 = fma2(a23, a23, qB23);
    }
}

// ---------------- conv contribution for one cg, compile-time dd half ------------
template<int DDB>
__device__ __forceinline__ void conv_half(const ulonglong2* __restrict__ vb,
                                          const ulonglong2* __restrict__ wcp,
                                          ull* cost)
{
    #pragma unroll
    for (int kh = 0; kh < 3; kh++) {
        #pragma unroll
        for (int kw = 0; kw < 3; kw++) {
            const ulonglong2* wp = wcp + (kh*3 + kw)*3;
            ulonglong2 w0 = wp[0], w1 = wp[1], w2 = wp[2];   // kd = 0,1,2
            #pragma unroll
            for (int j = 0; j < 4; j++) {
                const int dd = DDB + j;
                ulonglong2 v = vb[dd*PLANE + kh*HWs + kw];
                if (dd - 0 >= 0 && dd - 0 < TD) {
                    cost[dd-0] = fma2(v.x, w0.x, cost[dd-0]);
                    cost[dd-0] = fma2(v.y, w0.y, cost[dd-0]);
                }
                if (dd - 1 >= 0 && dd - 1 < TD) {
                    cost[dd-1] = fma2(v.x, w1.x, cost[dd-1]);
                    cost[dd-1] = fma2(v.y, w1.y, cost[dd-1]);
                }
                if (dd - 2 >= 0 && dd - 2 < TD) {
                    cost[dd-2] = fma2(v.x, w2.x, cost[dd-2]);
                    cost[dd-2] = fma2(v.y, w2.y, cost[dd-2]);
                }
            }
        }
    }
}

// ---------------- fused warp + variance + conv3d ----------------
__global__ __launch_bounds__(512, 1)
void fused_cost_kernel(const float* __restrict__ dvals) {
    extern __shared__ unsigned char smem_raw[];
    ulonglong2* sVar = (ulonglong2*)smem_raw;                 // [2][NHALO]
    float4*     sPos = (float4*)(smem_raw + OFF_POS);         // [NHALO]
    ull*        sWc  = (ull*)(smem_raw + OFF_WC);             // 432 u64
    float*      sMerge = (float*)(smem_raw + OFF_POS);        // aliases sPos (post-loop)

    const int tid = threadIdx.x;
    const int b  = blockIdx.z / NCHUNK;
    const int d0 = (blockIdx.z - b*NCHUNK) * TD;
    const int h0 = blockIdx.y * TH;
    const int w0 = blockIdx.x * TW;

    for (int i = tid; i < 864; i += 512) ((float*)sWc)[i] = g_wcf[i];

    float R[2][9], T[2][3];
    #pragma unroll
    for (int v = 0; v < 2; v++) {
        #pragma unroll
        for (int k = 0; k < 9; k++) R[v][k] = g_rot[b][v][k];
        #pragma unroll
        for (int k = 0; k < 3; k++) T[v][k] = g_trans[b][v][k];
    }

    // Phase 0: warped coords per (dd,p), rotation hoisted per p
    for (int p = tid; p < PLANE; p += 512) {
        int hh = p / HWs, ww = p - hh*HWs;
        int h = h0 + hh - 1, w = w0 + ww - 1;
        if ((unsigned)h >= (unsigned)NH || (unsigned)w >= (unsigned)NW) continue;
        float fx = (float)w, fy = (float)h;
        float rx[2], ry[2], rz[2];
        #pragma unroll
        for (int v = 0; v < 2; v++) {
            rx[v] = R[v][0]*fx + R[v][1]*fy + R[v][2];
            ry[v] = R[v][3]*fx + R[v][4]*fy + R[v][5];
            rz[v] = R[v][6]*fx + R[v][7]*fy + R[v][8];
        }
        #pragma unroll
        for (int dd = 0; dd < HD; dd++) {
            int d = d0 + dd - 1;
            if ((unsigned)d >= (unsigned)ND) continue;
            float dep = __ldg(&dvals[b*ND + d]);
            float res[4];
            #pragma unroll
            for (int v = 0; v < 2; v++) {
                float px = rx[v]*dep + T[v][0];
                float py = ry[v]*dep + T[v][1];
                float pz = rz[v]*dep + T[v][2];
                if (fabsf(pz) < 1e-6f) pz = 1e-6f;
                res[v*2+0] = px / pz;
                res[v*2+1] = py / pz;
            }
            sPos[dd*PLANE + p] = make_float4(res[0], res[1], res[2], res[3]);
        }
    }
    __syncthreads();

    const int t256 = tid & 255;
    const int lh = t256 >> 5;      // 0..7
    const int lw = t256 & 31;      // 0..31
    const bool halfA = (tid < 256);

    ull cost[TD];
    #pragma unroll
    for (int i = 0; i < TD; i++) cost[i] = 0;

    const ulonglong2* fbase = (const ulonglong2*)g_featT;

    #pragma unroll 1
    for (int pair = 0; pair < 4; pair++) {
        const int cgA = 2*pair, cgB = 2*pair + 1;
        const ulonglong2* refA = fbase + ((size_t)(0*NB + b)*8 + cgA)*CG_PLANE;
        const ulonglong2* refB = fbase + ((size_t)(0*NB + b)*8 + cgB)*CG_PLANE;
        const ulonglong2* v1A  = fbase + ((size_t)(1*NB + b)*8 + cgA)*CG_PLANE;
        const ulonglong2* v1B  = fbase + ((size_t)(1*NB + b)*8 + cgB)*CG_PLANE;
        const ulonglong2* v2A  = fbase + ((size_t)(2*NB + b)*8 + cgA)*CG_PLANE;
        const ulonglong2* v2B  = fbase + ((size_t)(2*NB + b)*8 + cgB)*CG_PLANE;

        // ---- Phase A: variance for halo volume, cg pair (desc computed once/8ch)
        for (int i = tid; i < NHALO; i += 512) {
            int dd = i / PLANE;
            int p  = i - dd*PLANE;
            int hh = p / HWs, ww = p - hh*HWs;
            int h = h0 + hh - 1, w = w0 + ww - 1;
            int d = d0 + dd - 1;
            ulonglong2 varA, varB;
            varA.x = 0; varA.y = 0; varB.x = 0; varB.y = 0;
            if ((unsigned)h < (unsigned)NH && (unsigned)w < (unsigned)NW &&
                (unsigned)d < (unsigned)ND) {
                int ro = h*NW + w;
                ulonglong2 rA = __ldg(refA + ro);
                ulonglong2 rB = __ldg(refB + ro);
                ull sA01 = rA.x, sA23 = rA.y, sB01 = rB.x, sB23 = rB.y;
                ull qA01 = mul2(rA.x, rA.x), qA23 = mul2(rA.y, rA.y);
                ull qB01 = mul2(rB.x, rB.x), qB23 = mul2(rB.y, rB.y);
                float4 P = sPos[i];
                interp_pair(v1A, v1B, P.x, P.y, sA01, sA23, qA01, qA23, sB01, sB23, qB01, qB23);
                interp_pair(v2A, v2B, P.z, P.w, sA01, sA23, qA01, qA23, sB01, sB23, qB01, qB23);
                ull m;
                m = mul2(sA01, INV3P); varA.x = fma2(m ^ NEGMASK, m, mul2(qA01, INV3P));
                m = mul2(sA23, INV3P); varA.y = fma2(m ^ NEGMASK, m, mul2(qA23, INV3P));
                m = mul2(sB01, INV3P); varB.x = fma2(m ^ NEGMASK, m, mul2(qB01, INV3P));
                m = mul2(sB23, INV3P); varB.y = fma2(m ^ NEGMASK, m, mul2(qB23, INV3P));
            }
            sVar[i] = varA;
            sVar[NHALO + i] = varB;
        }
        __syncthreads();

        // ---- Phase B: conv contributions, dd-range split across thread halves
        const ulonglong2* vbA = sVar + lh*HWs + lw;
        const ulonglong2* vbB = sVar + NHALO + lh*HWs + lw;
        const ulonglong2* wcA = (const ulonglong2*)sWc + cgA*27;
        const ulonglong2* wcB = (const ulonglong2*)sWc + cgB*27;
        if (halfA) {
            conv_half<0>(vbA, wcA, cost);
            conv_half<0>(vbB, wcB, cost);
        } else {
            conv_half<4>(vbA, wcA, cost);
            conv_half<4>(vbB, wcB, cost);
        }
        __syncthreads();
    }

    // ---- merge halves and store ----
    if (!halfA) {
        #pragma unroll
        for (int lo = 0; lo < TD; lo++)
            sMerge[t256*TD + lo] = sum2(cost[lo]);
    }
    __syncthreads();
    if (halfA) {
        const float bias = g_bias;
        #pragma unroll
        for (int lo = 0; lo < TD; lo++) {
            float val = sum2(cost[lo]) + sMerge[t256*TD + lo] + bias;
            g_cost[(((size_t)b*ND + d0 + lo)*NH + (h0 + lh))*NW + w0 + lw] = val;
        }
    }
}

// ---------------- softmax over depth + expected depth + confidence ----------------
__global__ __launch_bounds__(256)
void softmax_kernel(const float* __restrict__ dvals, float* __restrict__ out) {
    int gid = blockIdx.x*blockDim.x + threadIdx.x;
    if (gid >= NB*NHW) return;
    int b = gid / NHW;
    int hw = gid - b*NHW;
    const float* cp = g_cost + (size_t)b*ND*NHW + hw;
    float c[ND];
    float mx = -3.4e38f;
    #pragma unroll
    for (int d = 0; d < ND; d++) {
        c[d] = cp[(size_t)d*NHW];
        mx = fmaxf(mx, c[d]);
    }
    float sum = 0.f;
    #pragma unroll
    for (int d = 0; d < ND; d++) {
        c[d] = __expf(c[d] - mx);
        sum += c[d];
    }
    float inv = 1.f/sum;
    float depth = 0.f, fidx = 0.f;
    #pragma unroll
    for (int d = 0; d < ND; d++) {
        depth += c[d]*__ldg(&dvals[b*ND + d]);
        fidx  += c[d]*(float)d;
    }
    depth *= inv;
    fidx  *= inv;
    int di = (int)fidx;
    di = min(max(di, 0), ND-1);
    float conf = 0.f;
    #pragma unroll
    for (int d = 0; d < ND; d++) {
        if (d >= di-1 && d <= di+2) conf += c[d];
    }
    conf *= inv;
    out[gid] = depth;
    out[NB*NHW + gid] = conf;
}

// ---------------- launch ----------------
extern "C" void kernel_launch(void* const* d_in, const int* in_sizes, int n_in,
                              void* d_out, int out_size) {
    const float* features = (const float*)d_in[0];   // (V,B,C,H,W)
    const float* proj     = (const float*)d_in[1];   // (B,V,4,4)
    const float* dvals    = (const float*)d_in[2];   // (B,D)
    int iw = 3;
    while (iw < n_in && in_sizes[iw] != 27*NC) iw++;
    const float* rw = (const float*)d_in[iw];
    const float* rb = (const float*)d_in[iw+1];

    cudaFuncSetAttribute(fused_cost_kernel,
                         cudaFuncAttributeMaxDynamicSharedMemorySize, SMEM_BYTES);

    prep_kernel<<<1, 256>>>(proj, rw, rb);
    transpose_kernel<<<dim3(NHW/32, NV*NB), dim3(32, 8)>>>(features);
    fused_cost_kernel<<<dim3(NW/TW, NH/TH, NB*NCHUNK), 512, SMEM_BYTES>>>(dvals);
    softmax_kernel<<<(NB*NHW + 255)/256, 256>>>(dvals, (float*)d_out);
}

// round 8
// speedup vs baseline: 1.5992x; 1.0222x over previous
#include <cuda_runtime.h>
#include <math.h>

// ---------------- problem constants ----------------
#define NB 2
#define NV 3
#define NC 32
#define ND 48
#define NH 128
#define NW 160
#define NHW (NH*NW)          // 20480

typedef unsigned long long ull;

// ---------------- device scratch ----------------
// Feature layout: (V, B, cg=8, H, W, 4ch) fp32, pixel stride 16B
__device__ __align__(128) float g_featT[(size_t)NV*NB*NHW*NC];
// Variance volume: (B, cg=8, D, H, W, 4ch) fp32
__device__ __align__(128) float g_var[(size_t)NB*8*ND*NHW*4];
__device__ float g_cost[(size_t)NB*ND*NHW];
__device__ float g_rot[NB][2][9];
__device__ float g_trans[NB][2][3];
__device__ __align__(16) float g_wcf[864];   // [(cg*9 + kh*3 + kw)*12 + kd*4 + c4]
__device__ float g_bias;

// ---------------- packed f32x2 helpers ----------------
__device__ __forceinline__ ull fma2(ull a, ull b, ull c) {
    ull d; asm("fma.rn.f32x2 %0, %1, %2, %3;" : "=l"(d) : "l"(a), "l"(b), "l"(c)); return d;
}
__device__ __forceinline__ ull mul2(ull a, ull b) {
    ull d; asm("mul.rn.f32x2 %0, %1, %2;" : "=l"(d) : "l"(a), "l"(b)); return d;
}
__device__ __forceinline__ ull add2(ull a, ull b) {
    ull d; asm("add.rn.f32x2 %0, %1, %2;" : "=l"(d) : "l"(a), "l"(b)); return d;
}
__device__ __forceinline__ ull dup2(float f) {
    ull d; int r = __float_as_int(f);
    asm("mov.b64 %0, {%1, %1};" : "=l"(d) : "r"(r)); return d;
}
__device__ __forceinline__ float sum2(ull v) {
    int lo, hi; asm("mov.b64 {%0, %1}, %2;" : "=r"(lo), "=r"(hi) : "l"(v));
    return __int_as_float(lo) + __int_as_float(hi);
}
#define NEGMASK 0x8000000080000000ULL
#define INV3P   0x3eaaaaab3eaaaaabULL   // (1/3, 1/3)

// ---------------- prep: proj @ inv(ref_proj), weight relayout ----------------
__global__ void prep_kernel(const float* __restrict__ proj,
                            const float* __restrict__ rw,
                            const float* __restrict__ rb) {
    int tid = threadIdx.x;
    // rw layout (1,C,3,3,3): rw[c*27 + kd*9 + kh*3 + kw]
    for (int i = tid; i < 27*NC; i += blockDim.x) {
        int c = i / 27, k = i - c*27;
        int kd = k / 9, kh = (k - kd*9) / 3, kw = k % 3;
        int cg = c >> 2, c4 = c & 3;
        g_wcf[(cg*9 + kh*3 + kw)*12 + kd*4 + c4] = rw[i];
    }
    if (tid == 0) g_bias = rb[0];
    if (tid < NB) {
        int b = tid;
        const float* refp = proj + ((size_t)b*NV + 0)*16;
        double a[4][8];
        for (int r = 0; r < 4; r++)
            for (int c2 = 0; c2 < 4; c2++) {
                a[r][c2] = (double)refp[r*4+c2];
                a[r][4+c2] = (r == c2) ? 1.0 : 0.0;
            }
        for (int col = 0; col < 4; col++) {
            int p = col; double best = fabs(a[col][col]);
            for (int r = col+1; r < 4; r++) {
                double v = fabs(a[r][col]);
                if (v > best) { best = v; p = r; }
            }
            if (p != col)
                for (int c2 = 0; c2 < 8; c2++) {
                    double t = a[col][c2]; a[col][c2] = a[p][c2]; a[p][c2] = t;
                }
            double pi = 1.0 / a[col][col];
            for (int c2 = 0; c2 < 8; c2++) a[col][c2] *= pi;
            for (int r = 0; r < 4; r++) if (r != col) {
                double f = a[r][col];
                for (int c2 = 0; c2 < 8; c2++) a[r][c2] -= f*a[col][c2];
            }
        }
        for (int v = 1; v < NV; v++) {
            const float* S = proj + ((size_t)b*NV + v)*16;
            for (int r = 0; r < 3; r++) {
                double pr[4];
                for (int c2 = 0; c2 < 4; c2++) {
                    double s = 0.0;
                    for (int k = 0; k < 4; k++) s += (double)S[r*4+k]*a[k][4+c2];
                    pr[c2] = s;
                }
                g_rot[b][v-1][r*3+0] = (float)pr[0];
                g_rot[b][v-1][r*3+1] = (float)pr[1];
                g_rot[b][v-1][r*3+2] = (float)pr[2];
                g_trans[b][v-1][r]   = (float)pr[3];
            }
        }
    }
}

// ---------------- transpose (V,B,C,H,W) -> (V,B,cg,H,W,4) ----------------
__global__ void transpose_kernel(const float* __restrict__ feat) {
    __shared__ float t[32][33];
    int vb = blockIdx.y;
    int hw0 = blockIdx.x * 32;
    const float* src = feat + (size_t)vb*NC*NHW;
    #pragma unroll
    for (int cc = threadIdx.y; cc < 32; cc += 8)
        t[cc][threadIdx.x] = src[(size_t)cc*NHW + hw0 + threadIdx.x];
    __syncthreads();
    float* dst = g_featT + (size_t)vb*8*NHW*4;
    int c = threadIdx.x;
    int cg = c >> 2, c4 = c & 3;
    #pragma unroll
    for (int r = threadIdx.y; r < 32; r += 8)
        dst[((size_t)cg*NHW + hw0 + r)*4 + c4] = t[c][r];
}

// ---------------- bilinear descriptor + gather ----------------
__device__ __forceinline__ void make_desc(float px, float py, int* off, ull* wgt) {
    float x0f = floorf(px), y0f = floorf(py);
    float wx1 = px - x0f, wy1 = py - y0f;
    float wx0 = 1.f - wx1, wy0 = 1.f - wy1;
    float x1f = x0f + 1.f, y1f = y0f + 1.f;
    float vx0 = (x0f >= 0.f && x0f <= (float)(NW-1)) ? 1.f : 0.f;
    float vx1 = (x1f >= 0.f && x1f <= (float)(NW-1)) ? 1.f : 0.f;
    float vy0 = (y0f >= 0.f && y0f <= (float)(NH-1)) ? 1.f : 0.f;
    float vy1 = (y1f >= 0.f && y1f <= (float)(NH-1)) ? 1.f : 0.f;
    int ix0 = (int)fminf(fmaxf(x0f, 0.f), (float)(NW-1));
    int ix1 = (int)fminf(fmaxf(x1f, 0.f), (float)(NW-1));
    int iy0 = (int)fminf(fmaxf(y0f, 0.f), (float)(NH-1));
    int iy1 = (int)fminf(fmaxf(y1f, 0.f), (float)(NH-1));
    off[0] = iy0*NW+ix0; off[1] = iy0*NW+ix1;
    off[2] = iy1*NW+ix0; off[3] = iy1*NW+ix1;
    wgt[0] = dup2(wx0*wy0*vx0*vy0); wgt[1] = dup2(wx1*wy0*vx1*vy0);
    wgt[2] = dup2(wx0*wy1*vx0*vy1); wgt[3] = dup2(wx1*wy1*vx1*vy1);
}

__device__ __forceinline__ void gath(const ulonglong2* __restrict__ bp,
                                     const int* off, const ull* wgt,
                                     ull& s01, ull& s23, ull& q01, ull& q23) {
    ulonglong2 f0 = __ldg(bp+off[0]), f1 = __ldg(bp+off[1]);
    ulonglong2 f2 = __ldg(bp+off[2]), f3 = __ldg(bp+off[3]);
    ull a01 = mul2(f0.x, wgt[0]); a01 = fma2(f1.x, wgt[1], a01);
    a01 = fma2(f2.x, wgt[2], a01); a01 = fma2(f3.x, wgt[3], a01);
    ull a23 = mul2(f0.y, wgt[0]); a23 = fma2(f1.y, wgt[1], a23);
    a23 = fma2(f2.y, wgt[2], a23); a23 = fma2(f3.y, wgt[3], a23);
    s01 = add2(s01, a01); q01 = fma2(a01, a01, q01);
    s23 = add2(s23, a23); q23 = fma2(a23, a23, q23);
}

// ---------------- kernel V: warp + 3-view variance, no halo, no barriers -------
__global__ __launch_bounds__(256)
void var_kernel(const float* __restrict__ dvals) {
    int gid = blockIdx.x*256 + threadIdx.x;
    int w = gid % NW; int t = gid / NW;
    int h = t & (NH-1); t >>= 7;
    int d = t % ND; int b = t / ND;
    float dep = __ldg(&dvals[b*ND + d]);
    float fx = (float)w, fy = (float)h;

    int off[2][4]; ull wgt[2][4];
    #pragma unroll
    for (int v = 0; v < 2; v++) {
        float r0 = g_rot[b][v][0], r1 = g_rot[b][v][1], r2 = g_rot[b][v][2];
        float r3 = g_rot[b][v][3], r4 = g_rot[b][v][4], r5 = g_rot[b][v][5];
        float r6 = g_rot[b][v][6], r7 = g_rot[b][v][7], r8 = g_rot[b][v][8];
        float rx = r0*fx + r1*fy + r2;
        float ry = r3*fx + r4*fy + r5;
        float rz = r6*fx + r7*fy + r8;
        float px = rx*dep + g_trans[b][v][0];
        float py = ry*dep + g_trans[b][v][1];
        float pz = rz*dep + g_trans[b][v][2];
        if (fabsf(pz) < 1e-6f) pz = 1e-6f;
        make_desc(px/pz, py/pz, off[v], wgt[v]);
    }

    const ulonglong2* fb = (const ulonglong2*)g_featT;
    ulonglong2* gv = (ulonglong2*)g_var;
    const int ro = h*NW + w;
    const size_t outRow = (size_t)d*NHW + ro;

    #pragma unroll 1
    for (int pr = 0; pr < 4; pr++) {
        const int cgA = pr*2, cgB = cgA + 1;
        const ulonglong2* refA = fb + ((size_t)b*8 + cgA)*NHW;
        const ulonglong2* refB = refA + NHW;
        const ulonglong2* v1A  = fb + ((size_t)(NB + b)*8 + cgA)*NHW;
        const ulonglong2* v1B  = v1A + NHW;
        const ulonglong2* v2A  = fb + ((size_t)(2*NB + b)*8 + cgA)*NHW;
        const ulonglong2* v2B  = v2A + NHW;

        ulonglong2 rA = __ldg(refA + ro), rB = __ldg(refB + ro);
        ull sA01 = rA.x, sA23 = rA.y, sB01 = rB.x, sB23 = rB.y;
        ull qA01 = mul2(rA.x, rA.x), qA23 = mul2(rA.y, rA.y);
        ull qB01 = mul2(rB.x, rB.x), qB23 = mul2(rB.y, rB.y);

        gath(v1A, off[0], wgt[0], sA01, sA23, qA01, qA23);
        gath(v2A, off[1], wgt[1], sA01, sA23, qA01, qA23);
        gath(v1B, off[0], wgt[0], sB01, sB23, qB01, qB23);
        gath(v2B, off[1], wgt[1], sB01, sB23, qB01, qB23);

        ull m; ulonglong2 vA, vB;
        m = mul2(sA01, INV3P); vA.x = fma2(m ^ NEGMASK, m, mul2(qA01, INV3P));
        m = mul2(sA23, INV3P); vA.y = fma2(m ^ NEGMASK, m, mul2(qA23, INV3P));
        m = mul2(sB01, INV3P); vB.x = fma2(m ^ NEGMASK, m, mul2(qB01, INV3P));
        m = mul2(sB23, INV3P); vB.y = fma2(m ^ NEGMASK, m, mul2(qB23, INV3P));

        gv[((size_t)b*8 + cgA)*ND*NHW + outRow] = vA;
        gv[((size_t)b*8 + cgB)*ND*NHW + outRow] = vB;
    }
}

// ---------------- kernel C: tiled 3^3 conv over staged variance --------------
#define CTD 8
#define CTH 16
#define CTW 32
#define NZC (ND/CTD)         // 6
#define CHD (CTD+2)          // 10
#define CHHs (CTH+2)         // 18
#define CHWs (CTW+2)         // 34
#define CPLANE (CHHs*CHWs)   // 612
#define CVOL (CHD*CPLANE)    // 6120
#define CSMEM (CVOL*16 + 864*4)   // 101376 -> 2 blocks/SM

__global__ __launch_bounds__(256, 2)
void conv_kernel() {
    extern __shared__ unsigned char smem_raw[];
    ulonglong2* sV = (ulonglong2*)smem_raw;               // [CVOL]
    float*      sW = (float*)(smem_raw + CVOL*16);

    const int tid = threadIdx.x;
    const int b  = blockIdx.z / NZC;
    const int d0 = (blockIdx.z - b*NZC)*CTD;
    const int h0 = blockIdx.y * CTH;
    const int w0 = blockIdx.x * CTW;

    for (int i = tid; i < 864; i += 256) sW[i] = g_wcf[i];

    const int hl = tid >> 4;    // 0..15 output row
    const int wp = tid & 15;    // owns w = wp and wp+16

    ull acc[CTD][2];
    #pragma unroll
    for (int o = 0; o < CTD; o++) { acc[o][0] = 0; acc[o][1] = 0; }

    const ulonglong2* gv = (const ulonglong2*)g_var;

    #pragma unroll 1
    for (int cg = 0; cg < 8; cg++) {
        const ulonglong2* gvc = gv + ((size_t)b*8 + cg)*ND*NHW;
        // ---- load halo tile (coalesced, zero-fill OOB) ----
        for (int i = tid; i < CVOL; i += 256) {
            int hd = i / CPLANE;
            int p  = i - hd*CPLANE;
            int hh = p / CHWs;
            int ww = p - hh*CHWs;
            int d = d0 - 1 + hd, h = h0 + hh - 1, w = w0 + ww - 1;
            ulonglong2 v; v.x = 0; v.y = 0;
            if ((unsigned)d < (unsigned)ND && (unsigned)h < (unsigned)NH &&
                (unsigned)w < (unsigned)NW)
                v = __ldg(gvc + (size_t)d*NHW + h*NW + w);
            sV[i] = v;
        }
        __syncthreads();

        const ulonglong2* wc2 = (const ulonglong2*)sW + cg*27;
        #pragma unroll
        for (int kh = 0; kh < 3; kh++) {
            ulonglong2 wk[3][3];
            #pragma unroll
            for (int kw = 0; kw < 3; kw++)
                #pragma unroll
                for (int kd = 0; kd < 3; kd++)
                    wk[kw][kd] = wc2[(kh*3 + kw)*3 + kd];
            const ulonglong2* rowb = sV + (hl + kh)*CHWs + wp;
            #pragma unroll
            for (int hd = 0; hd < CHD; hd++) {
                const ulonglong2* row = rowb + hd*CPLANE;
                ulonglong2 t0 = row[0],  t1 = row[1],  t2 = row[2];
                ulonglong2 u0 = row[16], u1 = row[17], u2 = row[18];
                #pragma unroll
                for (int kd = 0; kd < 3; kd++) {
                    const int o = hd - kd;
                    if (o >= 0 && o < CTD) {
                        acc[o][0] = fma2(t0.x, wk[0][kd].x, acc[o][0]);
                        acc[o][0] = fma2(t0.y, wk[0][kd].y, acc[o][0]);
                        acc[o][0] = fma2(t1.x, wk[1][kd].x, acc[o][0]);
                        acc[o][0] = fma2(t1.y, wk[1][kd].y, acc[o][0]);
                        acc[o][0] = fma2(t2.x, wk[2][kd].x, acc[o][0]);
                        acc[o][0] = fma2(t2.y, wk[2][kd].y, acc[o][0]);
                        acc[o][1] = fma2(u0.x, wk[0][kd].x, acc[o][1]);
                        acc[o][1] = fma2(u0.y, wk[0][kd].y, acc[o][1]);
                        acc[o][1] = fma2(u1.x, wk[1][kd].x, acc[o][1]);
                        acc[o][1] = fma2(u1.y, wk[1][kd].y, acc[o][1]);
                        acc[o][1] = fma2(u2.x, wk[2][kd].x, acc[o][1]);
                        acc[o][1] = fma2(u2.y, wk[2][kd].y, acc[o][1]);
                    }
                }
            }
        }
        __syncthreads();
    }

    const float bias = g_bias;
    #pragma unroll
    for (int o = 0; o < CTD; o++) {
        size_t base = (((size_t)b*ND + d0 + o)*NH + (h0 + hl))*NW + w0;
        g_cost[base + wp]      = sum2(acc[o][0]) + bias;
        g_cost[base + wp + 16] = sum2(acc[o][1]) + bias;
    }
}

// ---------------- softmax over depth + expected depth + confidence ----------------
__global__ __launch_bounds__(256)
void softmax_kernel(const float* __restrict__ dvals, float* __restrict__ out) {
    int gid = blockIdx.x*blockDim.x + threadIdx.x;
    if (gid >= NB*NHW) return;
    int b = gid / NHW;
    int hw = gid - b*NHW;
    const float* cp = g_cost + (size_t)b*ND*NHW + hw;
    float c[ND];
    float mx = -3.4e38f;
    #pragma unroll
    for (int d = 0; d < ND; d++) {
        c[d] = cp[(size_t)d*NHW];
        mx = fmaxf(mx, c[d]);
    }
    float sum = 0.f;
    #pragma unroll
    for (int d = 0; d < ND; d++) {
        c[d] = __expf(c[d] - mx);
        sum += c[d];
    }
    float inv = 1.f/sum;
    float depth = 0.f, fidx = 0.f;
    #pragma unroll
    for (int d = 0; d < ND; d++) {
        depth += c[d]*__ldg(&dvals[b*ND + d]);
        fidx  += c[d]*(float)d;
    }
    depth *= inv;
    fidx  *= inv;
    int di = (int)fidx;
    di = min(max(di, 0), ND-1);
    float conf = 0.f;
    #pragma unroll
    for (int d = 0; d < ND; d++) {
        if (d >= di-1 && d <= di+2) conf += c[d];
    }
    conf *= inv;
    out[gid] = depth;
    out[NB*NHW + gid] = conf;
}

// ---------------- launch ----------------
extern "C" void kernel_launch(void* const* d_in, const int* in_sizes, int n_in,
                              void* d_out, int out_size) {
    const float* features = (const float*)d_in[0];   // (V,B,C,H,W)
    const float* proj     = (const float*)d_in[1];   // (B,V,4,4)
    const float* dvals    = (const float*)d_in[2];   // (B,D)
    int iw = 3;
    while (iw < n_in && in_sizes[iw] != 27*NC) iw++;
    const float* rw = (const float*)d_in[iw];
    const float* rb = (const float*)d_in[iw+1];

    cudaFuncSetAttribute(conv_kernel,
                         cudaFuncAttributeMaxDynamicSharedMemorySize, CSMEM);

    prep_kernel<<<1, 256>>>(proj, rw, rb);
    transpose_kernel<<<dim3(NHW/32, NV*NB), dim3(32, 8)>>>(features);
    var_kernel<<<(NB*ND*NHW)/256, 256>>>(dvals);
    conv_kernel<<<dim3(NW/CTW, NH/CTH, NB*NZC), 256, CSMEM>>>();
    softmax_kernel<<<(NB*NHW + 255)/256, 256>>>(dvals, (float*)d_out);
}

// round 9
// speedup vs baseline: 1.6722x; 1.0456x over previous
#include <cuda_runtime.h>
#include <cuda_fp16.h>
#include <math.h>

// ---------------- problem constants ----------------
#define NB 2
#define NV 3
#define NC 32
#define ND 48
#define NH 128
#define NW 160
#define NHW (NH*NW)          // 20480

typedef unsigned long long ull;

// ---------------- device scratch ----------------
// Feature layout: (V, B, cg=8, H, W, 4ch) fp32, pixel stride 16B
__device__ __align__(128) float g_featT[(size_t)NV*NB*NHW*NC];
// Variance volume fp16: (B, cg=8, D, H, W) x 4ch packed in uint2 (2x half2)
__device__ __align__(128) uint2 g_varH[(size_t)NB*8*ND*NHW];
__device__ float g_cost[(size_t)NB*ND*NHW];
__device__ float g_rot[NB][2][9];
__device__ float g_trans[NB][2][3];
__device__ __align__(16) float g_wcf[864];   // [(cg*9 + kh*3 + kw)*12 + kd*4 + c4]
__device__ float g_bias;

// ---------------- packed f32x2 helpers ----------------
__device__ __forceinline__ ull fma2(ull a, ull b, ull c) {
    ull d; asm("fma.rn.f32x2 %0, %1, %2, %3;" : "=l"(d) : "l"(a), "l"(b), "l"(c)); return d;
}
__device__ __forceinline__ ull mul2(ull a, ull b) {
    ull d; asm("mul.rn.f32x2 %0, %1, %2;" : "=l"(d) : "l"(a), "l"(b)); return d;
}
__device__ __forceinline__ ull add2(ull a, ull b) {
    ull d; asm("add.rn.f32x2 %0, %1, %2;" : "=l"(d) : "l"(a), "l"(b)); return d;
}
__device__ __forceinline__ ull dup2(float f) {
    ull d; int r = __float_as_int(f);
    asm("mov.b64 %0, {%1, %1};" : "=l"(d) : "r"(r)); return d;
}
__device__ __forceinline__ float sum2(ull v) {
    int lo, hi; asm("mov.b64 {%0, %1}, %2;" : "=r"(lo), "=r"(hi) : "l"(v));
    return __int_as_float(lo) + __int_as_float(hi);
}
// f32x2 (ull) -> half2 bits
__device__ __forceinline__ unsigned pkh2(ull v) {
    float lo, hi;
    asm("mov.b64 {%0, %1}, %2;" : "=f"(lo), "=f"(hi) : "l"(v));
    unsigned r;
    asm("cvt.rn.f16x2.f32 %0, %1, %2;" : "=r"(r) : "f"(hi), "f"(lo));
    return r;
}
// half2 bits -> f32x2 (ull)
__device__ __forceinline__ ull h2f2(unsigned h) {
    float lo, hi;
    asm("{ .reg .f16 l, u; mov.b32 {l, u}, %2; cvt.f32.f16 %0, l; cvt.f32.f16 %1, u; }"
        : "=f"(lo), "=f"(hi) : "r"(h));
    ull d; asm("mov.b64 %0, {%1, %2};" : "=l"(d) : "f"(lo), "f"(hi));
    return d;
}
#define NEGMASK 0x8000000080000000ULL
#define INV3P   0x3eaaaaab3eaaaaabULL   // (1/3, 1/3)

// ---------------- prep: proj @ inv(ref_proj), weight relayout ----------------
__global__ void prep_kernel(const float* __restrict__ proj,
                            const float* __restrict__ rw,
                            const float* __restrict__ rb) {
    int tid = threadIdx.x;
    for (int i = tid; i < 27*NC; i += blockDim.x) {
        int c = i / 27, k = i - c*27;
        int kd = k / 9, kh = (k - kd*9) / 3, kw = k % 3;
        int cg = c >> 2, c4 = c & 3;
        g_wcf[(cg*9 + kh*3 + kw)*12 + kd*4 + c4] = rw[i];
    }
    if (tid == 0) g_bias = rb[0];
    if (tid < NB) {
        int b = tid;
        const float* refp = proj + ((size_t)b*NV + 0)*16;
        double a[4][8];
        for (int r = 0; r < 4; r++)
            for (int c2 = 0; c2 < 4; c2++) {
                a[r][c2] = (double)refp[r*4+c2];
                a[r][4+c2] = (r == c2) ? 1.0 : 0.0;
            }
        for (int col = 0; col < 4; col++) {
            int p = col; double best = fabs(a[col][col]);
            for (int r = col+1; r < 4; r++) {
                double v = fabs(a[r][col]);
                if (v > best) { best = v; p = r; }
            }
            if (p != col)
                for (int c2 = 0; c2 < 8; c2++) {
                    double t = a[col][c2]; a[col][c2] = a[p][c2]; a[p][c2] = t;
                }
            double pi = 1.0 / a[col][col];
            for (int c2 = 0; c2 < 8; c2++) a[col][c2] *= pi;
            for (int r = 0; r < 4; r++) if (r != col) {
                double f = a[r][col];
                for (int c2 = 0; c2 < 8; c2++) a[r][c2] -= f*a[col][c2];
            }
        }
        for (int v = 1; v < NV; v++) {
            const float* S = proj + ((size_t)b*NV + v)*16;
            for (int r = 0; r < 3; r++) {
                double pr[4];
                for (int c2 = 0; c2 < 4; c2++) {
                    double s = 0.0;
                    for (int k = 0; k < 4; k++) s += (double)S[r*4+k]*a[k][4+c2];
                    pr[c2] = s;
                }
                g_rot[b][v-1][r*3+0] = (float)pr[0];
                g_rot[b][v-1][r*3+1] = (float)pr[1];
                g_rot[b][v-1][r*3+2] = (float)pr[2];
                g_trans[b][v-1][r]   = (float)pr[3];
            }
        }
    }
}

// ---------------- transpose (V,B,C,H,W) -> (V,B,cg,H,W,4) ----------------
__global__ void transpose_kernel(const float* __restrict__ feat) {
    __shared__ float t[32][33];
    int vb = blockIdx.y;
    int hw0 = blockIdx.x * 32;
    const float* src = feat + (size_t)vb*NC*NHW;
    #pragma unroll
    for (int cc = threadIdx.y; cc < 32; cc += 8)
        t[cc][threadIdx.x] = src[(size_t)cc*NHW + hw0 + threadIdx.x];
    __syncthreads();
    float* dst = g_featT + (size_t)vb*8*NHW*4;
    int c = threadIdx.x;
    int cg = c >> 2, c4 = c & 3;
    #pragma unroll
    for (int r = threadIdx.y; r < 32; r += 8)
        dst[((size_t)cg*NHW + hw0 + r)*4 + c4] = t[c][r];
}

// ---------------- bilinear descriptor + gather ----------------
__device__ __forceinline__ void make_desc(float px, float py, int* off, ull* wgt) {
    float x0f = floorf(px), y0f = floorf(py);
    float wx1 = px - x0f, wy1 = py - y0f;
    float wx0 = 1.f - wx1, wy0 = 1.f - wy1;
    float x1f = x0f + 1.f, y1f = y0f + 1.f;
    float vx0 = (x0f >= 0.f && x0f <= (float)(NW-1)) ? 1.f : 0.f;
    float vx1 = (x1f >= 0.f && x1f <= (float)(NW-1)) ? 1.f : 0.f;
    float vy0 = (y0f >= 0.f && y0f <= (float)(NH-1)) ? 1.f : 0.f;
    float vy1 = (y1f >= 0.f && y1f <= (float)(NH-1)) ? 1.f : 0.f;
    int ix0 = (int)fminf(fmaxf(x0f, 0.f), (float)(NW-1));
    int ix1 = (int)fminf(fmaxf(x1f, 0.f), (float)(NW-1));
    int iy0 = (int)fminf(fmaxf(y0f, 0.f), (float)(NH-1));
    int iy1 = (int)fminf(fmaxf(y1f, 0.f), (float)(NH-1));
    off[0] = iy0*NW+ix0; off[1] = iy0*NW+ix1;
    off[2] = iy1*NW+ix0; off[3] = iy1*NW+ix1;
    wgt[0] = dup2(wx0*wy0*vx0*vy0); wgt[1] = dup2(wx1*wy0*vx1*vy0);
    wgt[2] = dup2(wx0*wy1*vx0*vy1); wgt[3] = dup2(wx1*wy1*vx1*vy1);
}

__device__ __forceinline__ void gath(const ulonglong2* __restrict__ bp,
                                     const int* off, const ull* wgt,
                                     ull& s01, ull& s23, ull& q01, ull& q23) {
    ulonglong2 f0 = __ldg(bp+off[0]), f1 = __ldg(bp+off[1]);
    ulonglong2 f2 = __ldg(bp+off[2]), f3 = __ldg(bp+off[3]);
    ull a01 = mul2(f0.x, wgt[0]); a01 = fma2(f1.x, wgt[1], a01);
    a01 = fma2(f2.x, wgt[2], a01); a01 = fma2(f3.x, wgt[3], a01);
    ull a23 = mul2(f0.y, wgt[0]); a23 = fma2(f1.y, wgt[1], a23);
    a23 = fma2(f2.y, wgt[2], a23); a23 = fma2(f3.y, wgt[3], a23);
    s01 = add2(s01, a01); q01 = fma2(a01, a01, q01);
    s23 = add2(s23, a23); q23 = fma2(a23, a23, q23);
}

// ---------------- kernel V: warp + 3-view variance -> fp16 volume -------------
__global__ __launch_bounds__(256)
void var_kernel(const float* __restrict__ dvals) {
    int gid = blockIdx.x*256 + threadIdx.x;
    int w = gid % NW; int t = gid / NW;
    int h = t & (NH-1); t >>= 7;
    int d = t % ND; int b = t / ND;
    float dep = __ldg(&dvals[b*ND + d]);
    float fx = (float)w, fy = (float)h;

    int off[2][4]; ull wgt[2][4];
    #pragma unroll
    for (int v = 0; v < 2; v++) {
        float rx = g_rot[b][v][0]*fx + g_rot[b][v][1]*fy + g_rot[b][v][2];
        float ry = g_rot[b][v][3]*fx + g_rot[b][v][4]*fy + g_rot[b][v][5];
        float rz = g_rot[b][v][6]*fx + g_rot[b][v][7]*fy + g_rot[b][v][8];
        float px = rx*dep + g_trans[b][v][0];
        float py = ry*dep + g_trans[b][v][1];
        float pz = rz*dep + g_trans[b][v][2];
        if (fabsf(pz) < 1e-6f) pz = 1e-6f;
        make_desc(px/pz, py/pz, off[v], wgt[v]);
    }

    const ulonglong2* fb = (const ulonglong2*)g_featT;
    const int ro = h*NW + w;
    const size_t outRow = (size_t)d*NHW + ro;

    #pragma unroll 2
    for (int pr = 0; pr < 4; pr++) {
        const int cgA = pr*2, cgB = cgA + 1;
        const ulonglong2* refA = fb + ((size_t)b*8 + cgA)*NHW;
        const ulonglong2* refB = refA + NHW;
        const ulonglong2* v1A  = fb + ((size_t)(NB + b)*8 + cgA)*NHW;
        const ulonglong2* v1B  = v1A + NHW;
        const ulonglong2* v2A  = fb + ((size_t)(2*NB + b)*8 + cgA)*NHW;
        const ulonglong2* v2B  = v2A + NHW;

        ulonglong2 rA = __ldg(refA + ro), rB = __ldg(refB + ro);
        ull sA01 = rA.x, sA23 = rA.y, sB01 = rB.x, sB23 = rB.y;
        ull qA01 = mul2(rA.x, rA.x), qA23 = mul2(rA.y, rA.y);
        ull qB01 = mul2(rB.x, rB.x), qB23 = mul2(rB.y, rB.y);

        gath(v1A, off[0], wgt[0], sA01, sA23, qA01, qA23);
        gath(v2A, off[1], wgt[1], sA01, sA23, qA01, qA23);
        gath(v1B, off[0], wgt[0], sB01, sB23, qB01, qB23);
        gath(v2B, off[1], wgt[1], sB01, sB23, qB01, qB23);

        ull m, x01, x23;
        uint2 oA, oB;
        m = mul2(sA01, INV3P); x01 = fma2(m ^ NEGMASK, m, mul2(qA01, INV3P));
        m = mul2(sA23, INV3P); x23 = fma2(m ^ NEGMASK, m, mul2(qA23, INV3P));
        oA.x = pkh2(x01); oA.y = pkh2(x23);
        m = mul2(sB01, INV3P); x01 = fma2(m ^ NEGMASK, m, mul2(qB01, INV3P));
        m = mul2(sB23, INV3P); x23 = fma2(m ^ NEGMASK, m, mul2(qB23, INV3P));
        oB.x = pkh2(x01); oB.y = pkh2(x23);

        g_varH[((size_t)b*8 + cgA)*ND*NHW + outRow] = oA;
        g_varH[((size_t)b*8 + cgB)*ND*NHW + outRow] = oB;
    }
}

// ---------------- kernel C: tiled 3^3 conv over fp16 variance ----------------
#define CTD 8
#define CTH 16
#define CTW 32
#define NZC (ND/CTD)         // 6
#define CHD (CTD+2)          // 10
#define CHHs (CTH+2)         // 18
#define CHWs (CTW+2)         // 34
#define CPLANE (CHHs*CHWs)   // 612
#define CVOL (CHD*CPLANE)    // 6120
#define CSMEM (2*CVOL*8 + 864*4)   // 101376 -> 2 blocks/SM

__global__ __launch_bounds__(256, 2)
void conv_kernel() {
    extern __shared__ unsigned char smem_raw[];
    uint2* sVh = (uint2*)smem_raw;                        // [2][CVOL] fp16 pixels
    float* sW  = (float*)(smem_raw + 2*CVOL*8);

    const int tid = threadIdx.x;
    const int b  = blockIdx.z / NZC;
    const int d0 = (blockIdx.z - b*NZC)*CTD;
    const int h0 = blockIdx.y * CTH;
    const int w0 = blockIdx.x * CTW;

    for (int i = tid; i < 864; i += 256) sW[i] = g_wcf[i];

    const int hl = tid >> 4;        // 0..15 output row
    const int wp = (tid & 15) * 2;  // owns w = wp, wp+1 (adjacent pair)

    ull acc[CTD][2];
    #pragma unroll
    for (int o = 0; o < CTD; o++) { acc[o][0] = 0; acc[o][1] = 0; }

    #pragma unroll 1
    for (int ph = 0; ph < 4; ph++) {
        const int cg0 = 2*ph;
        // ---- load 2 cg halo tiles (coalesced uint2, zero-fill OOB) ----
        #pragma unroll 1
        for (int ci = 0; ci < 2; ci++) {
            const uint2* gvc = g_varH + ((size_t)b*8 + cg0 + ci)*ND*NHW;
            uint2* sVc = sVh + ci*CVOL;
            for (int i = tid; i < CVOL; i += 256) {
                int hd = i / CPLANE;
                int p  = i - hd*CPLANE;
                int hh = p / CHWs;
                int ww = p - hh*CHWs;
                int d = d0 - 1 + hd, h = h0 + hh - 1, w = w0 + ww - 1;
                uint2 v; v.x = 0; v.y = 0;
                if ((unsigned)d < (unsigned)ND && (unsigned)h < (unsigned)NH &&
                    (unsigned)w < (unsigned)NW)
                    v = __ldg(gvc + (size_t)d*NHW + h*NW + w);
                sVc[i] = v;
            }
        }
        __syncthreads();

        #pragma unroll 1
        for (int ci = 0; ci < 2; ci++) {
            const int cg = cg0 + ci;
            const uint2* sVc = sVh + ci*CVOL;
            const ulonglong2* wc2 = (const ulonglong2*)sW + cg*27;
            #pragma unroll
            for (int kh = 0; kh < 3; kh++) {
                ulonglong2 wk[3][3];   // [kw][kd]
                #pragma unroll
                for (int kw = 0; kw < 3; kw++)
                    #pragma unroll
                    for (int kd = 0; kd < 3; kd++)
                        wk[kw][kd] = wc2[(kh*3 + kw)*3 + kd];
                const uint2* rowb = sVc + (hl + kh)*CHWs + wp;
                #pragma unroll
                for (int hd = 0; hd < CHD; hd++) {
                    const uint2* row = rowb + hd*CPLANE;
                    uint4 va = *(const uint4*)(row);       // pixels wp-1+0, +1
                    uint4 vb = *(const uint4*)(row + 2);   // pixels +2, +3
                    ull c0a = h2f2(va.x), c0b = h2f2(va.y);
                    ull c1a = h2f2(va.z), c1b = h2f2(va.w);
                    ull c2a = h2f2(vb.x), c2b = h2f2(vb.y);
                    ull c3a = h2f2(vb.z), c3b = h2f2(vb.w);
                    #pragma unroll
                    for (int kd = 0; kd < 3; kd++) {
                        const int o = hd - kd;
                        if (o >= 0 && o < CTD) {
                            acc[o][0] = fma2(c0a, wk[0][kd].x, acc[o][0]);
                            acc[o][0] = fma2(c0b, wk[0][kd].y, acc[o][0]);
                            acc[o][0] = fma2(c1a, wk[1][kd].x, acc[o][0]);
                            acc[o][0] = fma2(c1b, wk[1][kd].y, acc[o][0]);
                            acc[o][0] = fma2(c2a, wk[2][kd].x, acc[o][0]);
                            acc[o][0] = fma2(c2b, wk[2][kd].y, acc[o][0]);
                            acc[o][1] = fma2(c1a, wk[0][kd].x, acc[o][1]);
                            acc[o][1] = fma2(c1b, wk[0][kd].y, acc[o][1]);
                            acc[o][1] = fma2(c2a, wk[1][kd].x, acc[o][1]);
                            acc[o][1] = fma2(c2b, wk[1][kd].y, acc[o][1]);
                            acc[o][1] = fma2(c3a, wk[2][kd].x, acc[o][1]);
                            acc[o][1] = fma2(c3b, wk[2][kd].y, acc[o][1]);
                        }
                    }
                }
            }
        }
        __syncthreads();
    }

    const float bias = g_bias;
    #pragma unroll
    for (int o = 0; o < CTD; o++) {
        size_t base = (((size_t)b*ND + d0 + o)*NH + (h0 + hl))*NW + w0 + wp;
        float2 r;
        r.x = sum2(acc[o][0]) + bias;
        r.y = sum2(acc[o][1]) + bias;
        *(float2*)(g_cost + base) = r;
    }
}

// ---------------- softmax over depth + expected depth + confidence ----------------
__global__ __launch_bounds__(256)
void softmax_kernel(const float* __restrict__ dvals, float* __restrict__ out) {
    int gid = blockIdx.x*blockDim.x + threadIdx.x;
    if (gid >= NB*NHW) return;
    int b = gid / NHW;
    int hw = gid - b*NHW;
    const float* cp = g_cost + (size_t)b*ND*NHW + hw;
    float c[ND];
    float mx = -3.4e38f;
    #pragma unroll
    for (int d = 0; d < ND; d++) {
        c[d] = cp[(size_t)d*NHW];
        mx = fmaxf(mx, c[d]);
    }
    float sum = 0.f;
    #pragma unroll
    for (int d = 0; d < ND; d++) {
        c[d] = __expf(c[d] - mx);
        sum += c[d];
    }
    float inv = 1.f/sum;
    float depth = 0.f, fidx = 0.f;
    #pragma unroll
    for (int d = 0; d < ND; d++) {
        depth += c[d]*__ldg(&dvals[b*ND + d]);
        fidx  += c[d]*(float)d;
    }
    depth *= inv;
    fidx  *= inv;
    int di = (int)fidx;
    di = min(max(di, 0), ND-1);
    float conf = 0.f;
    #pragma unroll
    for (int d = 0; d < ND; d++) {
        if (d >= di-1 && d <= di+2) conf += c[d];
    }
    conf *= inv;
    out[gid] = depth;
    out[NB*NHW + gid] = conf;
}

// ---------------- launch ----------------
extern "C" void kernel_launch(void* const* d_in, const int* in_sizes, int n_in,
                              void* d_out, int out_size) {
    const float* features = (const float*)d_in[0];   // (V,B,C,H,W)
    const float* proj     = (const float*)d_in[1];   // (B,V,4,4)
    const float* dvals    = (const float*)d_in[2];   // (B,D)
    int iw = 3;
    while (iw < n_in && in_sizes[iw] != 27*NC) iw++;
    const float* rw = (const float*)d_in[iw];
    const float* rb = (const float*)d_in[iw+1];

    cudaFuncSetAttribute(conv_kernel,
                         cudaFuncAttributeMaxDynamicSharedMemorySize, CSMEM);

    prep_kernel<<<1, 256>>>(proj, rw, rb);
    transpose_kernel<<<dim3(NHW/32, NV*NB), dim3(32, 8)>>>(features);
    var_kernel<<<(NB*ND*NHW)/256, 256>>>(dvals);
    conv_kernel<<<dim3(NW/CTW, NH/CTH, NB*NZC), 256, CSMEM>>>();
    softmax_kernel<<<(NB*NHW + 255)/256, 256>>>(dvals, (float*)d_out);
}

// round 11
// speedup vs baseline: 1.7500x; 1.0465x over previous
#include <cuda_runtime.h>
#include <cuda_fp16.h>
#include <math.h>

// ---------------- problem constants ----------------
#define NB 2
#define NV 3
#define NC 32
#define ND 48
#define NH 128
#define NW 160
#define NHW (NH*NW)          // 20480

typedef unsigned long long ull;

// ---------------- device scratch ----------------
// Feature layout: (V, B, cg=8, H, W, 4ch) fp32, pixel stride 16B
__device__ __align__(128) float g_featT[(size_t)NV*NB*NHW*NC];
// Variance volume fp16: (B, cg=8, D, H, W) x 4ch packed in uint2 (2x half2)
__device__ __align__(128) uint2 g_varH[(size_t)NB*8*ND*NHW];
__device__ float g_cost[(size_t)NB*ND*NHW];
__device__ float g_rot[NB][2][9];
__device__ float g_trans[NB][2][3];
// conv weights as float2 per (cg,chp,kh,kw,kd): [(cg*2+chp)*27 + (kh*3+kw)*3 + kd]
__device__ __align__(16) float g_wcf[864];
__device__ float g_bias;

// ---------------- packed f32x2 helpers ----------------
__device__ __forceinline__ ull fma2(ull a, ull b, ull c) {
    ull d; asm("fma.rn.f32x2 %0, %1, %2, %3;" : "=l"(d) : "l"(a), "l"(b), "l"(c)); return d;
}
__device__ __forceinline__ ull mul2(ull a, ull b) {
    ull d; asm("mul.rn.f32x2 %0, %1, %2;" : "=l"(d) : "l"(a), "l"(b)); return d;
}
__device__ __forceinline__ ull add2(ull a, ull b) {
    ull d; asm("add.rn.f32x2 %0, %1, %2;" : "=l"(d) : "l"(a), "l"(b)); return d;
}
__device__ __forceinline__ ull dup2(float f) {
    ull d; int r = __float_as_int(f);
    asm("mov.b64 %0, {%1, %1};" : "=l"(d) : "r"(r)); return d;
}
__device__ __forceinline__ float sum2(ull v) {
    int lo, hi; asm("mov.b64 {%0, %1}, %2;" : "=r"(lo), "=r"(hi) : "l"(v));
    return __int_as_float(lo) + __int_as_float(hi);
}
// f32x2 (ull) -> half2 bits
__device__ __forceinline__ unsigned pkh2(ull v) {
    float lo, hi;
    asm("mov.b64 {%0, %1}, %2;" : "=f"(lo), "=f"(hi) : "l"(v));
    unsigned r;
    asm("cvt.rn.f16x2.f32 %0, %1, %2;" : "=r"(r) : "f"(hi), "f"(lo));
    return r;
}
// half2 bits -> f32x2 (ull)
__device__ __forceinline__ ull h2f2(unsigned h) {
    float lo, hi;
    asm("{ .reg .f16 l, u; mov.b32 {l, u}, %2; cvt.f32.f16 %0, l; cvt.f32.f16 %1, u; }"
        : "=f"(lo), "=f"(hi) : "r"(h));
    ull d; asm("mov.b64 %0, {%1, %2};" : "=l"(d) : "f"(lo), "f"(hi));
    return d;
}
#define NEGMASK 0x8000000080000000ULL
#define INV3P   0x3eaaaaab3eaaaaabULL   // (1/3, 1/3)

// ---------------- prep: proj @ inv(ref_proj), weight relayout ----------------
__global__ void prep_kernel(const float* __restrict__ proj,
                            const float* __restrict__ rw,
                            const float* __restrict__ rb) {
    int tid = threadIdx.x;
    // rw layout (1,C,3,3,3): rw[c*27 + kd*9 + kh*3 + kw], c = cg*4 + chp*2 + lane
    for (int i = tid; i < 27*NC; i += blockDim.x) {
        int c = i / 27, k = i - c*27;
        int kd = k / 9, kh = (k - kd*9) / 3, kw = k % 3;
        int cg = c >> 2, chp = (c >> 1) & 1, lane = c & 1;
        g_wcf[(((cg*2 + chp)*27) + (kh*3 + kw)*3 + kd)*2 + lane] = rw[i];
    }
    if (tid == 0) g_bias = rb[0];
    if (tid < NB) {
        int b = tid;
        const float* refp = proj + ((size_t)b*NV + 0)*16;
        double a[4][8];
        for (int r = 0; r < 4; r++)
            for (int c2 = 0; c2 < 4; c2++) {
                a[r][c2] = (double)refp[r*4+c2];
                a[r][4+c2] = (r == c2) ? 1.0 : 0.0;
            }
        for (int col = 0; col < 4; col++) {
            int p = col; double best = fabs(a[col][col]);
            for (int r = col+1; r < 4; r++) {
                double v = fabs(a[r][col]);
                if (v > best) { best = v; p = r; }
            }
            if (p != col)
                for (int c2 = 0; c2 < 8; c2++) {
                    double t = a[col][c2]; a[col][c2] = a[p][c2]; a[p][c2] = t;
                }
            double pi = 1.0 / a[col][col];
            for (int c2 = 0; c2 < 8; c2++) a[col][c2] *= pi;
            for (int r = 0; r < 4; r++) if (r != col) {
                double f = a[r][col];
                for (int c2 = 0; c2 < 8; c2++) a[r][c2] -= f*a[col][c2];
            }
        }
        for (int v = 1; v < NV; v++) {
            const float* S = proj + ((size_t)b*NV + v)*16;
            for (int r = 0; r < 3; r++) {
                double pr[4];
                for (int c2 = 0; c2 < 4; c2++) {
                    double s = 0.0;
                    for (int k = 0; k < 4; k++) s += (double)S[r*4+k]*a[k][4+c2];
                    pr[c2] = s;
                }
                g_rot[b][v-1][r*3+0] = (float)pr[0];
                g_rot[b][v-1][r*3+1] = (float)pr[1];
                g_rot[b][v-1][r*3+2] = (float)pr[2];
                g_trans[b][v-1][r]   = (float)pr[3];
            }
        }
    }
}

// ---------------- transpose (V,B,C,H,W) -> (V,B,cg,H,W,4), coalesced STG.128 --
__global__ void transpose_kernel(const float* __restrict__ feat) {
    __shared__ float t[32][33];
    int vb = blockIdx.y;
    int hw0 = blockIdx.x * 32;
    const float* src = feat + (size_t)vb*NC*NHW;
    #pragma unroll
    for (int cc = threadIdx.y; cc < 32; cc += 8)
        t[cc][threadIdx.x] = src[(size_t)cc*NHW + hw0 + threadIdx.x];
    __syncthreads();
    int tx = threadIdx.x;     // pixel within group of 32
    int cg = threadIdx.y;     // 0..7
    float4 val = make_float4(t[4*cg+0][tx], t[4*cg+1][tx], t[4*cg+2][tx], t[4*cg+3][tx]);
    float4* dst = (float4*)g_featT + (size_t)vb*8*NHW + (size_t)cg*NHW + hw0 + tx;
    *dst = val;
}

// ---------------- bilinear descriptor + gather ----------------
__device__ __forceinline__ void make_desc(float px, float py, int* off, ull* wgt) {
    float x0f = floorf(px), y0f = floorf(py);
    float wx1 = px - x0f, wy1 = py - y0f;
    float wx0 = 1.f - wx1, wy0 = 1.f - wy1;
    float x1f = x0f + 1.f, y1f = y0f + 1.f;
    float vx0 = (x0f >= 0.f && x0f <= (float)(NW-1)) ? 1.f : 0.f;
    float vx1 = (x1f >= 0.f && x1f <= (float)(NW-1)) ? 1.f : 0.f;
    float vy0 = (y0f >= 0.f && y0f <= (float)(NH-1)) ? 1.f : 0.f;
    float vy1 = (y1f >= 0.f && y1f <= (float)(NH-1)) ? 1.f : 0.f;
    int ix0 = (int)fminf(fmaxf(x0f, 0.f), (float)(NW-1));
    int ix1 = (int)fminf(fmaxf(x1f, 0.f), (float)(NW-1));
    int iy0 = (int)fminf(fmaxf(y0f, 0.f), (float)(NH-1));
    int iy1 = (int)fminf(fmaxf(y1f, 0.f), (float)(NH-1));
    off[0] = iy0*NW+ix0; off[1] = iy0*NW+ix1;
    off[2] = iy1*NW+ix0; off[3] = iy1*NW+ix1;
    wgt[0] = dup2(wx0*wy0*vx0*vy0); wgt[1] = dup2(wx1*wy0*vx1*vy0);
    wgt[2] = dup2(wx0*wy1*vx0*vy1); wgt[3] = dup2(wx1*wy1*vx1*vy1);
}

__device__ __forceinline__ void gath(const ulonglong2* __restrict__ bp,
                                     const int* off, const ull* wgt,
                                     ull& s01, ull& s23, ull& q01, ull& q23) {
    ulonglong2 f0 = __ldg(bp+off[0]), f1 = __ldg(bp+off[1]);
    ulonglong2 f2 = __ldg(bp+off[2]), f3 = __ldg(bp+off[3]);
    ull a01 = mul2(f0.x, wgt[0]); a01 = fma2(f1.x, wgt[1], a01);
    a01 = fma2(f2.x, wgt[2], a01); a01 = fma2(f3.x, wgt[3], a01);
    ull a23 = mul2(f0.y, wgt[0]); a23 = fma2(f1.y, wgt[1], a23);
    a23 = fma2(f2.y, wgt[2], a23); a23 = fma2(f3.y, wgt[3], a23);
    s01 = add2(s01, a01); q01 = fma2(a01, a01, q01);
    s23 = add2(s23, a23); q23 = fma2(a23, a23, q23);
}

// ---------------- kernel V: warp + 3-view variance -> fp16 volume -------------
__global__ __launch_bounds__(256)
void var_kernel(const float* __restrict__ dvals) {
    int gid = blockIdx.x*256 + threadIdx.x;
    int w = gid % NW; int t = gid / NW;
    int h = t & (NH-1); t >>= 7;
    int d = t % ND; int b = t / ND;
    float dep = __ldg(&dvals[b*ND + d]);
    float fx = (float)w, fy = (float)h;

    int off[2][4]; ull wgt[2][4];
    #pragma unroll
    for (int v = 0; v < 2; v++) {
        float rx = g_rot[b][v][0]*fx + g_rot[b][v][1]*fy + g_rot[b][v][2];
        float ry = g_rot[b][v][3]*fx + g_rot[b][v][4]*fy + g_rot[b][v][5];
        float rz = g_rot[b][v][6]*fx + g_rot[b][v][7]*fy + g_rot[b][v][8];
        float px = rx*dep + g_trans[b][v][0];
        float py = ry*dep + g_trans[b][v][1];
        float pz = rz*dep + g_trans[b][v][2];
        if (fabsf(pz) < 1e-6f) pz = 1e-6f;
        make_desc(px/pz, py/pz, off[v], wgt[v]);
    }

    const ulonglong2* fb = (const ulonglong2*)g_featT;
    const int ro = h*NW + w;
    const size_t outRow = (size_t)d*NHW + ro;

    #pragma unroll 2
    for (int pr = 0; pr < 4; pr++) {
        const int cgA = pr*2, cgB = cgA + 1;
        const ulonglong2* refA = fb + ((size_t)b*8 + cgA)*NHW;
        const ulonglong2* refB = refA + NHW;
        const ulonglong2* v1A  = fb + ((size_t)(NB + b)*8 + cgA)*NHW;
        const ulonglong2* v1B  = v1A + NHW;
        const ulonglong2* v2A  = fb + ((size_t)(2*NB + b)*8 + cgA)*NHW;
        const ulonglong2* v2B  = v2A + NHW;

        ulonglong2 rA = __ldg(refA + ro), rB = __ldg(refB + ro);
        ull sA01 = rA.x, sA23 = rA.y, sB01 = rB.x, sB23 = rB.y;
        ull qA01 = mul2(rA.x, rA.x), qA23 = mul2(rA.y, rA.y);
        ull qB01 = mul2(rB.x, rB.x), qB23 = mul2(rB.y, rB.y);

        gath(v1A, off[0], wgt[0], sA01, sA23, qA01, qA23);
        gath(v2A, off[1], wgt[1], sA01, sA23, qA01, qA23);
        gath(v1B, off[0], wgt[0], sB01, sB23, qB01, qB23);
        gath(v2B, off[1], wgt[1], sB01, sB23, qB01, qB23);

        ull m, x01, x23;
        uint2 oA, oB;
        m = mul2(sA01, INV3P); x01 = fma2(m ^ NEGMASK, m, mul2(qA01, INV3P));
        m = mul2(sA23, INV3P); x23 = fma2(m ^ NEGMASK, m, mul2(qA23, INV3P));
        oA.x = pkh2(x01); oA.y = pkh2(x23);
        m = mul2(sB01, INV3P); x01 = fma2(m ^ NEGMASK, m, mul2(qB01, INV3P));
        m = mul2(sB23, INV3P); x23 = fma2(m ^ NEGMASK, m, mul2(qB23, INV3P));
        oB.x = pkh2(x01); oB.y = pkh2(x23);

        g_varH[((size_t)b*8 + cgA)*ND*NHW + outRow] = oA;
        g_varH[((size_t)b*8 + cgB)*ND*NHW + outRow] = oB;
    }
}

// ---------------- kernel C: tiled 3^3 conv, chpair-planar fp16 smem ----------
#define CTD 4
#define CTH 16
#define CTW 32
#define NZC (ND/CTD)         // 12
#define CHD (CTD+2)          // 6
#define CHHs (CTH+2)         // 18
#define CHWs (CTW+2)         // 34
#define CPLANE (CHHs*CHWs)   // 612
#define CVOL (CHD*CPLANE)    // 3672
// smem: sVh[2cg][2chp][CVOL] uint + weights
#define CSMEM (2*2*CVOL*4 + 864*4)   // 62208 -> 3 blocks/SM

__global__ __launch_bounds__(256, 3)
void conv_kernel() {
    extern __shared__ unsigned char smem_raw[];
    unsigned* sVh = (unsigned*)smem_raw;                  // [ci][chp][CVOL]
    float*    sW  = (float*)(smem_raw + 2*2*CVOL*4);

    const int tid = threadIdx.x;
    const int b  = blockIdx.z / NZC;
    const int d0 = (blockIdx.z - b*NZC)*CTD;
    const int h0 = blockIdx.y * CTH;
    const int w0 = blockIdx.x * CTW;

    for (int i = tid; i < 864; i += 256) sW[i] = g_wcf[i];

    const int hl = tid >> 4;        // 0..15 output row
    const int wp = (tid & 15) * 2;  // owns w = wp, wp+1

    ull acc[CTD][2];
    #pragma unroll
    for (int o = 0; o < CTD; o++) { acc[o][0] = 0; acc[o][1] = 0; }

    #pragma unroll 1
    for (int ph = 0; ph < 4; ph++) {
        const int cg0 = 2*ph;
        // ---- load 2 cg halo tiles, split channel pairs into planar smem ----
        #pragma unroll 1
        for (int ci = 0; ci < 2; ci++) {
            const uint2* gvc = g_varH + ((size_t)b*8 + cg0 + ci)*ND*NHW;
            unsigned* s0 = sVh + ci*2*CVOL;
            unsigned* s1 = s0 + CVOL;
            for (int i = tid; i < CVOL; i += 256) {
                int hd = i / CPLANE;
                int p  = i - hd*CPLANE;
                int hh = p / CHWs;
                int ww = p - hh*CHWs;
                int d = d0 - 1 + hd, h = h0 + hh - 1, w = w0 + ww - 1;
                uint2 v; v.x = 0; v.y = 0;
                if ((unsigned)d < (unsigned)ND && (unsigned)h < (unsigned)NH &&
                    (unsigned)w < (unsigned)NW)
                    v = __ldg(gvc + (size_t)d*NHW + h*NW + w);
                s0[i] = v.x;
                s1[i] = v.y;
            }
        }
        __syncthreads();

        #pragma unroll 1
        for (int ci = 0; ci < 2; ci++) {
            const int cg = cg0 + ci;
            #pragma unroll 1
            for (int chp = 0; chp < 2; chp++) {
                const unsigned* sVc = sVh + (ci*2 + chp)*CVOL;
                const ull* wb = (const ull*)sW + (cg*2 + chp)*27;
                #pragma unroll
                for (int kh = 0; kh < 3; kh++) {
                    // 9 packed ch-pair weights for this kh: [kw][kd]
                    ull wk[3][3];
                    #pragma unroll
                    for (int kw = 0; kw < 3; kw++)
                        #pragma unroll
                        for (int kd = 0; kd < 3; kd++)
                            wk[kw][kd] = wb[(kh*3 + kw)*3 + kd];
                    const unsigned* rowb = sVc + (hl + kh)*CHWs + wp;
                    #pragma unroll
                    for (int hd = 0; hd < CHD; hd++) {
                        // two aligned 8B loads (element index even): pixels wp..wp+3
                        uint2 vlo = *(const uint2*)(rowb + hd*CPLANE);
                        uint2 vhi = *(const uint2*)(rowb + hd*CPLANE + 2);
                        ull c0 = h2f2(vlo.x), c1 = h2f2(vlo.y);
                        ull c2 = h2f2(vhi.x), c3 = h2f2(vhi.y);
                        #pragma unroll
                        for (int kd = 0; kd < 3; kd++) {
                            const int o = hd - kd;
                            if (o >= 0 && o < CTD) {
                                acc[o][0] = fma2(c0, wk[0][kd], acc[o][0]);
                                acc[o][0] = fma2(c1, wk[1][kd], acc[o][0]);
                                acc[o][0] = fma2(c2, wk[2][kd], acc[o][0]);
                                acc[o][1] = fma2(c1, wk[0][kd], acc[o][1]);
                                acc[o][1] = fma2(c2, wk[1][kd], acc[o][1]);
                                acc[o][1] = fma2(c3, wk[2][kd], acc[o][1]);
                            }
                        }
                    }
                }
            }
        }
        __syncthreads();
    }

    const float bias = g_bias;
    #pragma unroll
    for (int o = 0; o < CTD; o++) {
        size_t base = (((size_t)b*ND + d0 + o)*NH + (h0 + hl))*NW + w0 + wp;
        float2 r;
        r.x = sum2(acc[o][0]) + bias;
        r.y = sum2(acc[o][1]) + bias;
        *(float2*)(g_cost + base) = r;
    }
}

// ---------------- softmax over depth + expected depth + confidence ----------------
__global__ __launch_bounds__(256)
void softmax_kernel(const float* __restrict__ dvals, float* __restrict__ out) {
    int gid = blockIdx.x*blockDim.x + threadIdx.x;
    if (gid >= NB*NHW) return;
    int b = gid / NHW;
    int hw = gid - b*NHW;
    const float* cp = g_cost + (size_t)b*ND*NHW + hw;
    float c[ND];
    float mx = -3.4e38f;
    #pragma unroll
    for (int d = 0; d < ND; d++) {
        c[d] = cp[(size_t)d*NHW];
        mx = fmaxf(mx, c[d]);
    }
    float sum = 0.f;
    #pragma unroll
    for (int d = 0; d < ND; d++) {
        c[d] = __expf(c[d] - mx);
        sum += c[d];
    }
    float inv = 1.f/sum;
    float depth = 0.f, fidx = 0.f;
    #pragma unroll
    for (int d = 0; d < ND; d++) {
        depth += c[d]*__ldg(&dvals[b*ND + d]);
        fidx  += c[d]*(float)d;
    }
    depth *= inv;
    fidx  *= inv;
    int di = (int)fidx;
    di = min(max(di, 0), ND-1);
    float conf = 0.f;
    #pragma unroll
    for (int d = 0; d < ND; d++) {
        if (d >= di-1 && d <= di+2) conf += c[d];
    }
    conf *= inv;
    out[gid] = depth;
    out[NB*NHW + gid] = conf;
}

// ---------------- launch ----------------
extern "C" void kernel_launch(void* const* d_in, const int* in_sizes, int n_in,
                              void* d_out, int out_size) {
    const float* features = (const float*)d_in[0];   // (V,B,C,H,W)
    const float* proj     = (const float*)d_in[1];   // (B,V,4,4)
    const float* dvals    = (const float*)d_in[2];   // (B,D)
    int iw = 3;
    while (iw < n_in && in_sizes[iw] != 27*NC) iw++;
    const float* rw = (const float*)d_in[iw];
    const float* rb = (const float*)d_in[iw+1];

    cudaFuncSetAttribute(conv_kernel,
                         cudaFuncAttributeMaxDynamicSharedMemorySize, CSMEM);

    prep_kernel<<<1, 256>>>(proj, rw, rb);
    transpose_kernel<<<dim3(NHW/32, NV*NB), dim3(32, 8)>>>(features);
    var_kernel<<<(NB*ND*NHW)/256, 256>>>(dvals);
    conv_kernel<<<dim3(NW/CTW, NH/CTH, NB*NZC), 256, CSMEM>>>();
    softmax_kernel<<<(NB*NHW + 255)/256, 256>>>(dvals, (float*)d_out);
}

// round 12
// speedup vs baseline: 1.9003x; 1.0859x over previous
#include <cuda_runtime.h>
#include <cuda_fp16.h>
#include <math.h>

// ---------------- problem constants ----------------
#define NB 2
#define NV 3
#define NC 32
#define ND 48
#define NH 128
#define NW 160
#define NHW (NH*NW)          // 20480

typedef unsigned long long ull;

// ---------------- device scratch ----------------
// Feature layout: (V, B, cg=8, H, W, 4ch) fp32, pixel stride 16B
__device__ __align__(128) float g_featT[(size_t)NV*NB*NHW*NC];
// Variance volume fp16: (B, cg=8, D, H, W) x 4ch packed in uint2 (2x half2)
__device__ __align__(128) uint2 g_varH[(size_t)NB*8*ND*NHW];
__device__ float g_cost[(size_t)NB*ND*NHW];
__device__ float g_rot[NB][2][9];
__device__ float g_trans[NB][2][3];
// conv weights as float2 per (cg,chp,kh,kw,kd): [(cg*2+chp)*27 + (kh*3+kw)*3 + kd]
__device__ __align__(16) float g_wcf[864];
__device__ float g_bias;

// ---------------- packed f32x2 helpers ----------------
__device__ __forceinline__ ull fma2(ull a, ull b, ull c) {
    ull d; asm("fma.rn.f32x2 %0, %1, %2, %3;" : "=l"(d) : "l"(a), "l"(b), "l"(c)); return d;
}
__device__ __forceinline__ ull mul2(ull a, ull b) {
    ull d; asm("mul.rn.f32x2 %0, %1, %2;" : "=l"(d) : "l"(a), "l"(b)); return d;
}
__device__ __forceinline__ ull add2(ull a, ull b) {
    ull d; asm("add.rn.f32x2 %0, %1, %2;" : "=l"(d) : "l"(a), "l"(b)); return d;
}
__device__ __forceinline__ ull dup2(float f) {
    ull d; int r = __float_as_int(f);
    asm("mov.b64 %0, {%1, %1};" : "=l"(d) : "r"(r)); return d;
}
__device__ __forceinline__ float sum2(ull v) {
    int lo, hi; asm("mov.b64 {%0, %1}, %2;" : "=r"(lo), "=r"(hi) : "l"(v));
    return __int_as_float(lo) + __int_as_float(hi);
}
// f32x2 (ull) -> half2 bits
__device__ __forceinline__ unsigned pkh2(ull v) {
    float lo, hi;
    asm("mov.b64 {%0, %1}, %2;" : "=f"(lo), "=f"(hi) : "l"(v));
    unsigned r;
    asm("cvt.rn.f16x2.f32 %0, %1, %2;" : "=r"(r) : "f"(hi), "f"(lo));
    return r;
}
// half2 bits -> f32x2 (ull)
__device__ __forceinline__ ull h2f2(unsigned h) {
    float lo, hi;
    asm("{ .reg .f16 l, u; mov.b32 {l, u}, %2; cvt.f32.f16 %0, l; cvt.f32.f16 %1, u; }"
        : "=f"(lo), "=f"(hi) : "r"(h));
    ull d; asm("mov.b64 %0, {%1, %2};" : "=l"(d) : "f"(lo), "f"(hi));
    return d;
}
#define NEGMASK 0x8000000080000000ULL
#define INV3P   0x3eaaaaab3eaaaaabULL   // (1/3, 1/3)

// ---------------- prep: proj @ inv(ref_proj), weight relayout ----------------
__global__ void prep_kernel(const float* __restrict__ proj,
                            const float* __restrict__ rw,
                            const float* __restrict__ rb) {
    int tid = threadIdx.x;
    // rw layout (1,C,3,3,3): rw[c*27 + kd*9 + kh*3 + kw], c = cg*4 + chp*2 + lane
    for (int i = tid; i < 27*NC; i += blockDim.x) {
        int c = i / 27, k = i - c*27;
        int kd = k / 9, kh = (k - kd*9) / 3, kw = k % 3;
        int cg = c >> 2, chp = (c >> 1) & 1, lane = c & 1;
        g_wcf[(((cg*2 + chp)*27) + (kh*3 + kw)*3 + kd)*2 + lane] = rw[i];
    }
    if (tid == 0) g_bias = rb[0];
    if (tid < NB) {
        int b = tid;
        const float* refp = proj + ((size_t)b*NV + 0)*16;
        double a[4][8];
        for (int r = 0; r < 4; r++)
            for (int c2 = 0; c2 < 4; c2++) {
                a[r][c2] = (double)refp[r*4+c2];
                a[r][4+c2] = (r == c2) ? 1.0 : 0.0;
            }
        for (int col = 0; col < 4; col++) {
            int p = col; double best = fabs(a[col][col]);
            for (int r = col+1; r < 4; r++) {
                double v = fabs(a[r][col]);
                if (v > best) { best = v; p = r; }
            }
            if (p != col)
                for (int c2 = 0; c2 < 8; c2++) {
                    double t = a[col][c2]; a[col][c2] = a[p][c2]; a[p][c2] = t;
                }
            double pi = 1.0 / a[col][col];
            for (int c2 = 0; c2 < 8; c2++) a[col][c2] *= pi;
            for (int r = 0; r < 4; r++) if (r != col) {
                double f = a[r][col];
                for (int c2 = 0; c2 < 8; c2++) a[r][c2] -= f*a[col][c2];
            }
        }
        for (int v = 1; v < NV; v++) {
            const float* S = proj + ((size_t)b*NV + v)*16;
            for (int r = 0; r < 3; r++) {
                double pr[4];
                for (int c2 = 0; c2 < 4; c2++) {
                    double s = 0.0;
                    for (int k = 0; k < 4; k++) s += (double)S[r*4+k]*a[k][4+c2];
                    pr[c2] = s;
                }
                g_rot[b][v-1][r*3+0] = (float)pr[0];
                g_rot[b][v-1][r*3+1] = (float)pr[1];
                g_rot[b][v-1][r*3+2] = (float)pr[2];
                g_trans[b][v-1][r]   = (float)pr[3];
            }
        }
    }
}

// ---------------- transpose (V,B,C,H,W) -> (V,B,cg,H,W,4), coalesced STG.128 --
__global__ void transpose_kernel(const float* __restrict__ feat) {
    __shared__ float t[32][33];
    int vb = blockIdx.y;
    int hw0 = blockIdx.x * 32;
    const float* src = feat + (size_t)vb*NC*NHW;
    #pragma unroll
    for (int cc = threadIdx.y; cc < 32; cc += 8)
        t[cc][threadIdx.x] = src[(size_t)cc*NHW + hw0 + threadIdx.x];
    __syncthreads();
    int tx = threadIdx.x;     // pixel within group of 32
    int cg = threadIdx.y;     // 0..7
    float4 val = make_float4(t[4*cg+0][tx], t[4*cg+1][tx], t[4*cg+2][tx], t[4*cg+3][tx]);
    float4* dst = (float4*)g_featT + (size_t)vb*8*NHW + (size_t)cg*NHW + hw0 + tx;
    *dst = val;
}

// ---------------- bilinear descriptor + gather ----------------
__device__ __forceinline__ void make_desc(float px, float py, int* off, ull* wgt) {
    float x0f = floorf(px), y0f = floorf(py);
    float wx1 = px - x0f, wy1 = py - y0f;
    float wx0 = 1.f - wx1, wy0 = 1.f - wy1;
    float x1f = x0f + 1.f, y1f = y0f + 1.f;
    float vx0 = (x0f >= 0.f && x0f <= (float)(NW-1)) ? 1.f : 0.f;
    float vx1 = (x1f >= 0.f && x1f <= (float)(NW-1)) ? 1.f : 0.f;
    float vy0 = (y0f >= 0.f && y0f <= (float)(NH-1)) ? 1.f : 0.f;
    float vy1 = (y1f >= 0.f && y1f <= (float)(NH-1)) ? 1.f : 0.f;
    int ix0 = (int)fminf(fmaxf(x0f, 0.f), (float)(NW-1));
    int ix1 = (int)fminf(fmaxf(x1f, 0.f), (float)(NW-1));
    int iy0 = (int)fminf(fmaxf(y0f, 0.f), (float)(NH-1));
    int iy1 = (int)fminf(fmaxf(y1f, 0.f), (float)(NH-1));
    off[0] = iy0*NW+ix0; off[1] = iy0*NW+ix1;
    off[2] = iy1*NW+ix0; off[3] = iy1*NW+ix1;
    wgt[0] = dup2(wx0*wy0*vx0*vy0); wgt[1] = dup2(wx1*wy0*vx1*vy0);
    wgt[2] = dup2(wx0*wy1*vx0*vy1); wgt[3] = dup2(wx1*wy1*vx1*vy1);
}

__device__ __forceinline__ void gath(const ulonglong2* __restrict__ bp,
                                     const int* off, const ull* wgt,
                                     ull& s01, ull& s23, ull& q01, ull& q23) {
    ulonglong2 f0 = __ldg(bp+off[0]), f1 = __ldg(bp+off[1]);
    ulonglong2 f2 = __ldg(bp+off[2]), f3 = __ldg(bp+off[3]);
    ull a01 = mul2(f0.x, wgt[0]); a01 = fma2(f1.x, wgt[1], a01);
    a01 = fma2(f2.x, wgt[2], a01); a01 = fma2(f3.x, wgt[3], a01);
    ull a23 = mul2(f0.y, wgt[0]); a23 = fma2(f1.y, wgt[1], a23);
    a23 = fma2(f2.y, wgt[2], a23); a23 = fma2(f3.y, wgt[3], a23);
    s01 = add2(s01, a01); q01 = fma2(a01, a01, q01);
    s23 = add2(s23, a23); q23 = fma2(a23, a23, q23);
}

// ---------------- kernel V: warp + 3-view variance -> fp16 volume -------------
__global__ __launch_bounds__(256)
void var_kernel(const float* __restrict__ dvals) {
    int gid = blockIdx.x*256 + threadIdx.x;
    int w = gid % NW; int t = gid / NW;
    int h = t & (NH-1); t >>= 7;
    int d = t % ND; int b = t / ND;
    float dep = __ldg(&dvals[b*ND + d]);
    float fx = (float)w, fy = (float)h;

    int off[2][4]; ull wgt[2][4];
    #pragma unroll
    for (int v = 0; v < 2; v++) {
        float rx = g_rot[b][v][0]*fx + g_rot[b][v][1]*fy + g_rot[b][v][2];
        float ry = g_rot[b][v][3]*fx + g_rot[b][v][4]*fy + g_rot[b][v][5];
        float rz = g_rot[b][v][6]*fx + g_rot[b][v][7]*fy + g_rot[b][v][8];
        float px = rx*dep + g_trans[b][v][0];
        float py = ry*dep + g_trans[b][v][1];
        float pz = rz*dep + g_trans[b][v][2];
        if (fabsf(pz) < 1e-6f) pz = 1e-6f;
        make_desc(px/pz, py/pz, off[v], wgt[v]);
    }

    const ulonglong2* fb = (const ulonglong2*)g_featT;
    const int ro = h*NW + w;
    const size_t outRow = (size_t)d*NHW + ro;

    #pragma unroll 2
    for (int pr = 0; pr < 4; pr++) {
        const int cgA = pr*2, cgB = cgA + 1;
        const ulonglong2* refA = fb + ((size_t)b*8 + cgA)*NHW;
        const ulonglong2* refB = refA + NHW;
        const ulonglong2* v1A  = fb + ((size_t)(NB + b)*8 + cgA)*NHW;
        const ulonglong2* v1B  = v1A + NHW;
        const ulonglong2* v2A  = fb + ((size_t)(2*NB + b)*8 + cgA)*NHW;
        const ulonglong2* v2B  = v2A + NHW;

        ulonglong2 rA = __ldg(refA + ro), rB = __ldg(refB + ro);
        ull sA01 = rA.x, sA23 = rA.y, sB01 = rB.x, sB23 = rB.y;
        ull qA01 = mul2(rA.x, rA.x), qA23 = mul2(rA.y, rA.y);
        ull qB01 = mul2(rB.x, rB.x), qB23 = mul2(rB.y, rB.y);

        gath(v1A, off[0], wgt[0], sA01, sA23, qA01, qA23);
        gath(v2A, off[1], wgt[1], sA01, sA23, qA01, qA23);
        gath(v1B, off[0], wgt[0], sB01, sB23, qB01, qB23);
        gath(v2B, off[1], wgt[1], sB01, sB23, qB01, qB23);

        ull m, x01, x23;
        uint2 oA, oB;
        m = mul2(sA01, INV3P); x01 = fma2(m ^ NEGMASK, m, mul2(qA01, INV3P));
        m = mul2(sA23, INV3P); x23 = fma2(m ^ NEGMASK, m, mul2(qA23, INV3P));
        oA.x = pkh2(x01); oA.y = pkh2(x23);
        m = mul2(sB01, INV3P); x01 = fma2(m ^ NEGMASK, m, mul2(qB01, INV3P));
        m = mul2(sB23, INV3P); x23 = fma2(m ^ NEGMASK, m, mul2(qB23, INV3P));
        oB.x = pkh2(x01); oB.y = pkh2(x23);

        g_varH[((size_t)b*8 + cgA)*ND*NHW + outRow] = oA;
        g_varH[((size_t)b*8 + cgB)*ND*NHW + outRow] = oB;
    }
}

// ---------------- kernel C: tiled 3^3 conv, fp32-planar smem (cvt on load) ----
#define CTD 4
#define CTH 16
#define CTW 32
#define NZC (ND/CTD)         // 12
#define CHD (CTD+2)          // 6
#define CHHs (CTH+2)         // 18
#define CHWs (CTW+2)         // 34
#define CPLANE (CHHs*CHWs)   // 612
#define CVOL (CHD*CPLANE)    // 3672
// smem: sV[2 chp][CVOL] f32-pairs (ull) + weights
#define CSMEM (2*CVOL*8 + 864*4)   // 62208 -> 3 blocks/SM

__global__ __launch_bounds__(256, 3)
void conv_kernel() {
    extern __shared__ unsigned char smem_raw[];
    ull*   s0 = (ull*)smem_raw;            // chp 0 plane: f32x2 per pixel
    ull*   s1 = s0 + CVOL;                 // chp 1 plane
    float* sW = (float*)(smem_raw + 2*CVOL*8);

    const int tid = threadIdx.x;
    const int b  = blockIdx.z / NZC;
    const int d0 = (blockIdx.z - b*NZC)*CTD;
    const int h0 = blockIdx.y * CTH;
    const int w0 = blockIdx.x * CTW;

    for (int i = tid; i < 864; i += 256) sW[i] = g_wcf[i];

    const int hl = tid >> 4;        // 0..15 output row
    const int wp = (tid & 15) * 2;  // owns w = wp, wp+1

    ull acc[CTD][2];
    #pragma unroll
    for (int o = 0; o < CTD; o++) { acc[o][0] = 0; acc[o][1] = 0; }

    #pragma unroll 1
    for (int cg = 0; cg < 8; cg++) {
        // ---- load halo tile: fp16 gmem -> fp32 planar smem (convert ONCE) ----
        const uint2* gvc = g_varH + ((size_t)b*8 + cg)*ND*NHW;
        for (int i = tid; i < CVOL; i += 256) {
            int hd = i / CPLANE;
            int p  = i - hd*CPLANE;
            int hh = p / CHWs;
            int ww = p - hh*CHWs;
            int d = d0 - 1 + hd, h = h0 + hh - 1, w = w0 + ww - 1;
            uint2 v; v.x = 0; v.y = 0;
            if ((unsigned)d < (unsigned)ND && (unsigned)h < (unsigned)NH &&
                (unsigned)w < (unsigned)NW)
                v = __ldg(gvc + (size_t)d*NHW + h*NW + w);
            s0[i] = h2f2(v.x);
            s1[i] = h2f2(v.y);
        }
        __syncthreads();

        #pragma unroll 1
        for (int chp = 0; chp < 2; chp++) {
            const ull* sVc = chp ? s1 : s0;
            const ull* wb = (const ull*)sW + (cg*2 + chp)*27;
            #pragma unroll
            for (int kh = 0; kh < 3; kh++) {
                ull wk[3][3];   // [kw][kd] packed ch-pair weights
                #pragma unroll
                for (int kw = 0; kw < 3; kw++)
                    #pragma unroll
                    for (int kd = 0; kd < 3; kd++)
                        wk[kw][kd] = wb[(kh*3 + kw)*3 + kd];
                const ull* rowb = sVc + (hl + kh)*CHWs + wp;
                #pragma unroll
                for (int hd = 0; hd < CHD; hd++) {
                    // even ull index -> 16B aligned; 2x LDS.128, 4 pixels fp32
                    ulonglong2 va = *(const ulonglong2*)(rowb + hd*CPLANE);
                    ulonglong2 vb = *(const ulonglong2*)(rowb + hd*CPLANE + 2);
                    ull c0 = va.x, c1 = va.y, c2 = vb.x, c3 = vb.y;
                    #pragma unroll
                    for (int kd = 0; kd < 3; kd++) {
                        const int o = hd - kd;
                        if (o >= 0 && o < CTD) {
                            acc[o][0] = fma2(c0, wk[0][kd], acc[o][0]);
                            acc[o][0] = fma2(c1, wk[1][kd], acc[o][0]);
                            acc[o][0] = fma2(c2, wk[2][kd], acc[o][0]);
                            acc[o][1] = fma2(c1, wk[0][kd], acc[o][1]);
                            acc[o][1] = fma2(c2, wk[1][kd], acc[o][1]);
                            acc[o][1] = fma2(c3, wk[2][kd], acc[o][1]);
                        }
                    }
                }
            }
        }
        __syncthreads();
    }

    const float bias = g_bias;
    #pragma unroll
    for (int o = 0; o < CTD; o++) {
        size_t base = (((size_t)b*ND + d0 + o)*NH + (h0 + hl))*NW + w0 + wp;
        float2 r;
        r.x = sum2(acc[o][0]) + bias;
        r.y = sum2(acc[o][1]) + bias;
        *(float2*)(g_cost + base) = r;
    }
}

// ---------------- softmax over depth + expected depth + confidence ----------------
__global__ __launch_bounds__(256)
void softmax_kernel(const float* __restrict__ dvals, float* __restrict__ out) {
    int gid = blockIdx.x*blockDim.x + threadIdx.x;
    if (gid >= NB*NHW) return;
    int b = gid / NHW;
    int hw = gid - b*NHW;
    const float* cp = g_cost + (size_t)b*ND*NHW + hw;
    float c[ND];
    float mx = -3.4e38f;
    #pragma unroll
    for (int d = 0; d < ND; d++) {
        c[d] = cp[(size_t)d*NHW];
        mx = fmaxf(mx, c[d]);
    }
    float sum = 0.f;
    #pragma unroll
    for (int d = 0; d < ND; d++) {
        c[d] = __expf(c[d] - mx);
        sum += c[d];
    }
    float inv = 1.f/sum;
    float depth = 0.f, fidx = 0.f;
    #pragma unroll
    for (int d = 0; d < ND; d++) {
        depth += c[d]*__ldg(&dvals[b*ND + d]);
        fidx  += c[d]*(float)d;
    }
    depth *= inv;
    fidx  *= inv;
    int di = (int)fidx;
    di = min(max(di, 0), ND-1);
    float conf = 0.f;
    #pragma unroll
    for (int d = 0; d < ND; d++) {
        if (d >= di-1 && d <= di+2) conf += c[d];
    }
    conf *= inv;
    out[gid] = depth;
    out[NB*NHW + gid] = conf;
}

// ---------------- launch ----------------
extern "C" void kernel_launch(void* const* d_in, const int* in_sizes, int n_in,
                              void* d_out, int out_size) {
    const float* features = (const float*)d_in[0];   // (V,B,C,H,W)
    const float* proj     = (const float*)d_in[1];   // (B,V,4,4)
    const float* dvals    = (const float*)d_in[2];   // (B,D)
    int iw = 3;
    while (iw < n_in && in_sizes[iw] != 27*NC) iw++;
    const float* rw = (const float*)d_in[iw];
    const float* rb = (const float*)d_in[iw+1];

    cudaFuncSetAttribute(conv_kernel,
                         cudaFuncAttributeMaxDynamicSharedMemorySize, CSMEM);

    prep_kernel<<<1, 256>>>(proj, rw, rb);
    transpose_kernel<<<dim3(NHW/32, NV*NB), dim3(32, 8)>>>(features);
    var_kernel<<<(NB*ND*NHW)/256, 256>>>(dvals);
    conv_kernel<<<dim3(NW/CTW, NH/CTH, NB*NZC), 256, CSMEM>>>();
    softmax_kernel<<<(NB*NHW + 255)/256, 256>>>(dvals, (float*)d_out);
}